// round 1
// baseline (speedup 1.0000x reference)
#include <cuda_runtime.h>
#include <math.h>

// ---------------- problem constants ----------------
#define Bn   4
#define Cn   512
#define Hn   768
#define NHn  12
#define NEn  20
#define MMn  23
#define Pn   380
#define BPn  1520          // B*P
#define QSn  128
#define EMBn 768
#define NBn  12
#define BLKn 64
#define NCLSn 97
#define POSn 128

static __device__ __constant__ float kNEG = -10000.0f;
#define SCALE_EMB 0.03608439182435161f   // 1/sqrt(768)

// ---------------- scratch (single static device buffer) ----------------
#define OFF_ENT_EMB 0UL                                   // 1840*768
#define OFF_ENT_ATT (OFF_ENT_EMB + 1840UL*768)            // 960*512
#define OFF_ENT_Q   (OFF_ENT_ATT + 960UL*512)             // 1840*128
#define OFF_HT_ATT  (OFF_ENT_Q   + 1840UL*128)            // 1520*512
#define OFF_RS      (OFF_HT_ATT  + 1520UL*512)            // 1520*768
#define OFF_HTQ     (OFF_RS      + 1520UL*768)            // 1520*128
#define OFF_HS_ATT  (OFF_HTQ     + 1520UL*128)            // 1520*768
#define OFF_TS_ATT  (OFF_HS_ATT  + 1520UL*768)
#define OFF_CAT_H   (OFF_TS_ATT  + 1520UL*768)            // 1520*1536
#define OFF_CAT_T   (OFF_CAT_H   + 1520UL*1536)
#define OFF_HS      (OFF_CAT_T   + 1520UL*1536)           // 1520*768
#define OFF_TS      (OFF_HS      + 1520UL*768)
#define OFF_PAIRG   (OFF_TS      + 1520UL*768)
#define OFF_CATPP   (OFF_PAIRG   + 1520UL*768)            // 1520*1024
#define OFF_PAIR1   (OFF_CATPP   + 1520UL*1024)
#define OFF_QB      (OFF_PAIR1   + 1520UL*768)
#define OFF_KB      (OFF_QB      + 1520UL*768)
#define OFF_VB      (OFF_KB      + 1520UL*768)
#define OFF_SC      (OFF_VB      + 1520UL*768)            // 4*380*380
#define OFF_ATTO    (OFF_SC      + 4UL*380*380)
#define OFF_CATF    (OFF_ATTO    + 1520UL*768)            // 1520*2304
#define OFF_H1      (OFF_CATF    + 1520UL*2304)
#define SCRATCH_TOTAL (OFF_H1    + 1520UL*768)

__device__ float g_scratch[SCRATCH_TOTAL];

// ---------------- generic SGEMM: C = act(alpha*A@B(+bias)) ----------------
// A: M x K row-major (lda).  B: K x N (ldb) or, if TRANSB, N x K (ldb).
// Batched via grid.z with element strides sA/sB/sC.
template<bool TRANSB, bool BIAS, bool TANH>
__global__ void sgemm_k(const float* __restrict__ A, const float* __restrict__ Bm,
                        const float* __restrict__ bias, float* __restrict__ Cm,
                        int M, int N, int K, int lda, int ldb, int ldc,
                        long sA, long sB, long sC, float alpha)
{
    __shared__ float As[16][64];
    __shared__ float Bs[16][64];
    const int tid = threadIdx.x;                 // 256 threads
    const int tx = tid & 15, ty = tid >> 4;
    const int m0 = blockIdx.y * 64, n0 = blockIdx.x * 64;
    A  += (long)blockIdx.z * sA;
    Bm += (long)blockIdx.z * sB;
    Cm += (long)blockIdx.z * sC;
    float acc[4][4] = {};
    const int am = tid >> 2, ak = (tid & 3) << 2;

    for (int k0 = 0; k0 < K; k0 += 16) {
        // ---- A tile (transposed into As[k][m]) ----
        {
            const bool mok = (m0 + am) < M;
            const float* Ap = A + (long)(m0 + am) * lda + (k0 + ak);
            #pragma unroll
            for (int i = 0; i < 4; ++i) {
                float v = 0.f;
                if (mok && (k0 + ak + i) < K) v = Ap[i];
                As[ak + i][am] = v;
            }
        }
        // ---- B tile ----
        if (!TRANSB) {
            const int bk = tid >> 4, bn = (tid & 15) << 2;
            const bool kok = (k0 + bk) < K;
            const float* Bp = Bm + (long)(k0 + bk) * ldb + (n0 + bn);
            #pragma unroll
            for (int i = 0; i < 4; ++i) {
                float v = 0.f;
                if (kok && (n0 + bn + i) < N) v = Bp[i];
                Bs[bk][bn + i] = v;
            }
        } else {
            const int bn = tid >> 2, bk = (tid & 3) << 2;
            const bool nok = (n0 + bn) < N;
            const float* Bp = Bm + (long)(n0 + bn) * ldb + (k0 + bk);
            #pragma unroll
            for (int i = 0; i < 4; ++i) {
                float v = 0.f;
                if (nok && (k0 + bk + i) < K) v = Bp[i];
                Bs[bk + i][bn] = v;
            }
        }
        __syncthreads();
        #pragma unroll
        for (int kk = 0; kk < 16; ++kk) {
            float4 ra = *reinterpret_cast<const float4*>(&As[kk][ty << 2]);
            float4 rb = *reinterpret_cast<const float4*>(&Bs[kk][tx << 2]);
            float a_[4] = {ra.x, ra.y, ra.z, ra.w};
            float b_[4] = {rb.x, rb.y, rb.z, rb.w};
            #pragma unroll
            for (int i = 0; i < 4; ++i)
                #pragma unroll
                for (int j = 0; j < 4; ++j)
                    acc[i][j] = fmaf(a_[i], b_[j], acc[i][j]);
        }
        __syncthreads();
    }
    #pragma unroll
    for (int i = 0; i < 4; ++i) {
        const int m = m0 + (ty << 2) + i;
        if (m >= M) continue;
        #pragma unroll
        for (int j = 0; j < 4; ++j) {
            const int n = n0 + (tx << 2) + j;
            if (n >= N) continue;
            float v = acc[i][j] * alpha;
            if (BIAS) v += bias[n];
            if (TANH) v = tanhf(v);
            Cm[(long)m * ldc + n] = v;
        }
    }
}

// ---------------- implicit bilinear GEMM ----------------
// C[m,n] = sum_{nb,i,j} Hs[m,nb*64+i]*Ts[m,nb*64+j]*W[(nb*4096+i*64+j), n] + bias[n]
__global__ void bilinear_k(const float* __restrict__ Hs, const float* __restrict__ Ts,
                           const float* __restrict__ W, const float* __restrict__ bias,
                           float* __restrict__ Cm, int M)
{
    __shared__ float bh_s[64][64];
    __shared__ float bt_s[64][64];
    __shared__ float Bs[64][64];
    const int tid = threadIdx.x;                // 256 threads
    const int tx = tid & 15, ty = tid >> 4;
    const int m0 = blockIdx.y * 64, n0 = blockIdx.x * 64;
    float acc[4][4] = {};

    for (int nb = 0; nb < NBn; ++nb) {
        __syncthreads();                         // protect bh/bt reuse
        for (int t = tid; t < 4096; t += 256) {
            const int p = t >> 6, i = t & 63;
            const int m = m0 + p;
            float hv = 0.f, tv = 0.f;
            if (m < M) {
                hv = Hs[(long)m * 768 + nb * 64 + i];
                tv = Ts[(long)m * 768 + nb * 64 + i];
            }
            bh_s[p][i] = hv;
            bt_s[p][i] = tv;
        }
        __syncthreads();
        for (int i = 0; i < 64; ++i) {
            __syncthreads();                     // protect Bs reuse
            for (int t = tid; t < 4096; t += 256) {
                const int j = t >> 6, nn = t & 63;
                Bs[j][nn] = W[(long)(nb * 4096 + i * 64 + j) * 768 + n0 + nn];
            }
            __syncthreads();
            const int r0 = ty << 2;
            const float bh0 = bh_s[r0 + 0][i];
            const float bh1 = bh_s[r0 + 1][i];
            const float bh2 = bh_s[r0 + 2][i];
            const float bh3 = bh_s[r0 + 3][i];
            #pragma unroll 8
            for (int j = 0; j < 64; ++j) {
                float4 rb = *reinterpret_cast<const float4*>(&Bs[j][tx << 2]);
                const float a0 = bh0 * bt_s[r0 + 0][j];
                const float a1 = bh1 * bt_s[r0 + 1][j];
                const float a2 = bh2 * bt_s[r0 + 2][j];
                const float a3 = bh3 * bt_s[r0 + 3][j];
                acc[0][0] = fmaf(a0, rb.x, acc[0][0]); acc[0][1] = fmaf(a0, rb.y, acc[0][1]);
                acc[0][2] = fmaf(a0, rb.z, acc[0][2]); acc[0][3] = fmaf(a0, rb.w, acc[0][3]);
                acc[1][0] = fmaf(a1, rb.x, acc[1][0]); acc[1][1] = fmaf(a1, rb.y, acc[1][1]);
                acc[1][2] = fmaf(a1, rb.z, acc[1][2]); acc[1][3] = fmaf(a1, rb.w, acc[1][3]);
                acc[2][0] = fmaf(a2, rb.x, acc[2][0]); acc[2][1] = fmaf(a2, rb.y, acc[2][1]);
                acc[2][2] = fmaf(a2, rb.z, acc[2][2]); acc[2][3] = fmaf(a2, rb.w, acc[2][3]);
                acc[3][0] = fmaf(a3, rb.x, acc[3][0]); acc[3][1] = fmaf(a3, rb.y, acc[3][1]);
                acc[3][2] = fmaf(a3, rb.z, acc[3][2]); acc[3][3] = fmaf(a3, rb.w, acc[3][3]);
            }
        }
    }
    #pragma unroll
    for (int i = 0; i < 4; ++i) {
        const int m = m0 + (ty << 2) + i;
        if (m >= M) continue;
        #pragma unroll
        for (int j = 0; j < 4; ++j) {
            const int n = n0 + (tx << 2) + j;
            Cm[(long)m * 768 + n] = acc[i][j] + bias[n];
        }
    }
}

// ---------------- small fused kernels ----------------
// ent_emb[b,e,m,:] = mask * seq[b, idx, :]
__global__ void ent_emb_k(const float* __restrict__ seq, const int* __restrict__ midx,
                          const float* __restrict__ mmask, float* __restrict__ ent_emb)
{
    const int blk = blockIdx.x;                 // b*NE*MM
    const int m = blk % MMn;
    const int e = (blk / MMn) % NEn;
    const int b = blk / (MMn * NEn);
    (void)m; (void)e;
    const int idx = midx[blk];
    const float mask = mmask[blk];
    const float* src = seq + ((long)b * Cn + idx) * Hn;
    float* dst = ent_emb + (long)blk * Hn;
    for (int h = threadIdx.x; h < Hn; h += 256) dst[h] = mask * src[h];
}

// ent_att[b,e,nh,c] = sum_m mask*att[b,nh,idx_m,c] / cnt
__global__ void ent_att_k(const float* __restrict__ att, const int* __restrict__ midx,
                          const float* __restrict__ mmask, float* __restrict__ ent_att)
{
    const int blk = blockIdx.x;                 // b*NE*NH
    const int nh = blk % NHn;
    const int e  = (blk / NHn) % NEn;
    const int b  = blk / (NHn * NEn);
    const int c  = threadIdx.x;                 // 512
    const int* mi = midx + (b * NEn + e) * MMn;
    const float* mk = mmask + (b * NEn + e) * MMn;
    float cnt = 0.f, s = 0.f;
    for (int m = 0; m < MMn; ++m) {
        const float w = mk[m];
        cnt += w;
        s += w * att[(((long)b * NHn + nh) * Cn + mi[m]) * Cn + c];
    }
    ent_att[(long)blk * Cn + c] = s / cnt;
}

// ht_att[b,p,c] = norm_c( mean_nh ent_att[b,hi,nh,c]*ent_att[b,ti,nh,c] )
__global__ void ht_att_k(const float* __restrict__ ent_att, const int* __restrict__ hts,
                         float* __restrict__ ht_att)
{
    const int bp = blockIdx.x;
    const int b = bp / Pn;
    const int hi = hts[bp * 2], ti = hts[bp * 2 + 1];
    const int c = threadIdx.x;                  // 512
    const float* ha = ent_att + (long)(b * NEn + hi) * NHn * Cn;
    const float* ta = ent_att + (long)(b * NEn + ti) * NHn * Cn;
    float v = 0.f;
    #pragma unroll
    for (int nh = 0; nh < NHn; ++nh) v += ha[nh * Cn + c] * ta[nh * Cn + c];
    v *= (1.f / 12.f);
    __shared__ float red[512];
    red[c] = v; __syncthreads();
    for (int s = 256; s > 0; s >>= 1) { if (c < s) red[c] += red[c + s]; __syncthreads(); }
    ht_att[(long)bp * Cn + c] = v / (red[0] + 1e-5f);
}

// mention-pooling: softmax over mentions, pooled embedding
__global__ void pool_attn_k(const float* __restrict__ htq, const float* __restrict__ ent_q,
                            const float* __restrict__ ent_emb, const float* __restrict__ mmask,
                            const int* __restrict__ hts, float* __restrict__ hs_att,
                            float* __restrict__ ts_att)
{
    const int bp = blockIdx.x;
    const int side = blockIdx.y;                // 0=head, 1=tail
    const int b = bp / Pn;
    const int e = hts[bp * 2 + side];
    __shared__ float qs[QSn];
    __shared__ float gs[MMn];
    const int tid = threadIdx.x;                // 256
    if (tid < QSn) qs[tid] = htq[(long)bp * QSn + tid];
    __syncthreads();
    if (tid < MMn) {
        const float* eq = ent_q + ((long)(b * NEn + e) * MMn + tid) * QSn;
        float d = 0.f;
        for (int i = 0; i < QSn; ++i) d += qs[i] * eq[i];
        const float mk = mmask[(b * NEn + e) * MMn + tid];
        gs[tid] = (mk > 0.f) ? d * SCALE_EMB : kNEG;
    }
    __syncthreads();
    float mx = -1e30f;
    for (int m = 0; m < MMn; ++m) mx = fmaxf(mx, gs[m]);
    float w[MMn]; float ssum = 0.f;
    for (int m = 0; m < MMn; ++m) { w[m] = expf(gs[m] - mx); ssum += w[m]; }
    const float inv = 1.f / ssum;
    const float* emb = ent_emb + (long)(b * NEn + e) * MMn * Hn;
    float* out = (side ? ts_att : hs_att) + (long)bp * Hn;
    for (int h = tid; h < Hn; h += 256) {
        float acc = 0.f;
        for (int m = 0; m < MMn; ++m) acc += w[m] * emb[m * Hn + h];
        out[h] = acc * inv;
    }
}

__global__ void cat2_k(const float* __restrict__ hs_att, const float* __restrict__ ts_att,
                       const float* __restrict__ rs, float* __restrict__ cat_h,
                       float* __restrict__ cat_t)
{
    const long r = blockIdx.x;
    for (int h = threadIdx.x; h < Hn; h += 256) {
        const float rv = rs[r * Hn + h];
        cat_h[r * 1536 + h]       = hs_att[r * Hn + h];
        cat_h[r * 1536 + 768 + h] = rv;
        cat_t[r * 1536 + h]       = ts_att[r * Hn + h];
        cat_t[r * 1536 + 768 + h] = rv;
    }
}

__global__ void catpp_k(const float* __restrict__ pairg, const float* __restrict__ pos_emb,
                        const int* __restrict__ hts, float* __restrict__ catpp)
{
    const long r = blockIdx.x;
    const int hi = hts[r * 2], ti = hts[r * 2 + 1];
    if (threadIdx.x < POSn) {
        catpp[r * 1024 + threadIdx.x]       = pos_emb[hi * POSn + threadIdx.x];
        catpp[r * 1024 + 896 + threadIdx.x] = pos_emb[ti * POSn + threadIdx.x];
    }
    for (int h = threadIdx.x; h < Hn; h += 256)
        catpp[r * 1024 + 128 + h] = pairg[r * Hn + h];
}

__global__ void pair_softmax_k(float* __restrict__ sc, const float* __restrict__ vis)
{
    const long bp = blockIdx.x;                 // 0..1519
    float* row = sc + bp * Pn;
    const float* vr = vis + bp * Pn;
    const int tid = threadIdx.x;                // 128
    __shared__ float red[128];
    float mx = -1e30f;
    for (int q = tid; q < Pn; q += 128) {
        const float v = (vr[q] > 0.f) ? row[q] : kNEG;
        mx = fmaxf(mx, v);
    }
    red[tid] = mx; __syncthreads();
    for (int s = 64; s > 0; s >>= 1) { if (tid < s) red[tid] = fmaxf(red[tid], red[tid + s]); __syncthreads(); }
    mx = red[0]; __syncthreads();
    float sum = 0.f;
    for (int q = tid; q < Pn; q += 128) {
        const float v = (vr[q] > 0.f) ? row[q] : kNEG;
        sum += expf(v - mx);
    }
    red[tid] = sum; __syncthreads();
    for (int s = 64; s > 0; s >>= 1) { if (tid < s) red[tid] += red[tid + s]; __syncthreads(); }
    const float inv = 1.f / red[0];
    for (int q = tid; q < Pn; q += 128) {
        const float v = (vr[q] > 0.f) ? row[q] : kNEG;
        row[q] = expf(v - mx) * inv;
    }
}

__global__ void catfeat_k(const float* __restrict__ hs, const float* __restrict__ ts,
                          const float* __restrict__ pair1, const float* __restrict__ atto,
                          float* __restrict__ catf)
{
    const long r = blockIdx.x;
    for (int h = threadIdx.x; h < Hn; h += 256) {
        catf[r * 2304 + h]        = hs[r * Hn + h];
        catf[r * 2304 + 768 + h]  = ts[r * Hn + h];
        catf[r * 2304 + 1536 + h] = pair1[r * Hn + h] + atto[r * Hn + h];
    }
}

// ---------------- launcher ----------------
extern "C" void kernel_launch(void* const* d_in, const int* in_sizes, int n_in,
                              void* d_out, int out_size)
{
    (void)in_sizes; (void)n_in; (void)out_size;
    const float* seq   = (const float*)d_in[0];
    const float* att   = (const float*)d_in[1];
    const int*   midx  = (const int*)  d_in[2];
    const float* mmask = (const float*)d_in[3];
    const int*   hts   = (const int*)  d_in[4];
    const float* vis   = (const float*)d_in[5];
    const float* Wcq = (const float*)d_in[6],  *bcq = (const float*)d_in[7];
    const float* Weq = (const float*)d_in[8],  *beq = (const float*)d_in[9];
    const float* Whe = (const float*)d_in[10], *bhe = (const float*)d_in[11];
    const float* Wte = (const float*)d_in[12], *bte = (const float*)d_in[13];
    const float* Wbl = (const float*)d_in[14], *bbl = (const float*)d_in[15];
    const float* Wpp = (const float*)d_in[16], *bpp = (const float*)d_in[17];
    const float* Wgq = (const float*)d_in[18];
    const float* Wgk = (const float*)d_in[19];
    const float* Wgv = (const float*)d_in[20];
    const float* Wp1 = (const float*)d_in[21], *bp1 = (const float*)d_in[22];
    const float* Wp2 = (const float*)d_in[23], *bp2 = (const float*)d_in[24];
    const float* pos = (const float*)d_in[25];
    float* out = (float*)d_out;

    float* base = nullptr;
    cudaGetSymbolAddress((void**)&base, g_scratch);
    float* ent_emb = base + OFF_ENT_EMB;
    float* ent_att = base + OFF_ENT_ATT;
    float* ent_q   = base + OFF_ENT_Q;
    float* ht_att  = base + OFF_HT_ATT;
    float* rs      = base + OFF_RS;
    float* htqb    = base + OFF_HTQ;
    float* hs_att  = base + OFF_HS_ATT;
    float* ts_att  = base + OFF_TS_ATT;
    float* cat_h   = base + OFF_CAT_H;
    float* cat_t   = base + OFF_CAT_T;
    float* hs_t    = base + OFF_HS;
    float* ts_t    = base + OFF_TS;
    float* pairg   = base + OFF_PAIRG;
    float* catpp   = base + OFF_CATPP;
    float* pair1   = base + OFF_PAIR1;
    float* qb      = base + OFF_QB;
    float* kb      = base + OFF_KB;
    float* vb      = base + OFF_VB;
    float* scb     = base + OFF_SC;
    float* atto    = base + OFF_ATTO;
    float* catf    = base + OFF_CATF;
    float* h1      = base + OFF_H1;

    // 1) entity gathers
    ent_emb_k<<<Bn * NEn * MMn, 256>>>(seq, midx, mmask, ent_emb);
    ent_att_k<<<Bn * NEn * NHn, 512>>>(att, midx, mmask, ent_att);
    // 2) pair attention over context + normalization
    ht_att_k<<<BPn, 512>>>(ent_att, hts, ht_att);
    // 3) rs = ht_att @ seq  (batched [380,512]@[512,768])
    sgemm_k<false,false,false><<<dim3(12, 6, 4), 256>>>(ht_att, seq, nullptr, rs,
        Pn, Hn, Cn, Cn, Hn, Hn, 380L*512, 512L*768, 380L*768, 1.f);
    // 4) htq = rs@Wcq+bcq ; ent_q = ent_emb@Weq+beq
    sgemm_k<false,true,false><<<dim3(2, 24, 1), 256>>>(rs, Wcq, bcq, htqb,
        BPn, QSn, Hn, Hn, QSn, QSn, 0, 0, 0, 1.f);
    sgemm_k<false,true,false><<<dim3(2, 29, 1), 256>>>(ent_emb, Weq, beq, ent_q,
        1840, QSn, Hn, Hn, QSn, QSn, 0, 0, 0, 1.f);
    // 5) mention-pool softmax (head+tail)
    pool_attn_k<<<dim3(BPn, 2), 256>>>(htqb, ent_q, ent_emb, mmask, hts, hs_att, ts_att);
    // 6) hs/ts projections with tanh
    cat2_k<<<BPn, 256>>>(hs_att, ts_att, rs, cat_h, cat_t);
    sgemm_k<false,true,true><<<dim3(12, 24, 1), 256>>>(cat_h, Whe, bhe, hs_t,
        BPn, EMBn, 1536, 1536, EMBn, EMBn, 0, 0, 0, 1.f);
    sgemm_k<false,true,true><<<dim3(12, 24, 1), 256>>>(cat_t, Wte, bte, ts_t,
        BPn, EMBn, 1536, 1536, EMBn, EMBn, 0, 0, 0, 1.f);
    // 7) grouped bilinear (implicit [1520,49152]@[49152,768])
    bilinear_k<<<dim3(12, 24), 256>>>(hs_t, ts_t, Wbl, bbl, pairg, BPn);
    // 8) positional concat + Wpp tanh
    catpp_k<<<BPn, 256>>>(pairg, pos, hts, catpp);
    sgemm_k<false,true,true><<<dim3(12, 24, 1), 256>>>(catpp, Wpp, bpp, pair1,
        BPn, EMBn, 1024, 1024, EMBn, EMBn, 0, 0, 0, 1.f);
    // 9) pair-graph attention
    sgemm_k<false,false,false><<<dim3(12, 24, 1), 256>>>(pair1, Wgq, nullptr, qb,
        BPn, EMBn, EMBn, EMBn, EMBn, EMBn, 0, 0, 0, 1.f);
    sgemm_k<false,false,false><<<dim3(12, 24, 1), 256>>>(pair1, Wgk, nullptr, kb,
        BPn, EMBn, EMBn, EMBn, EMBn, EMBn, 0, 0, 0, 1.f);
    sgemm_k<false,false,false><<<dim3(12, 24, 1), 256>>>(pair1, Wgv, nullptr, vb,
        BPn, EMBn, EMBn, EMBn, EMBn, EMBn, 0, 0, 0, 1.f);
    sgemm_k<true,false,false><<<dim3(6, 6, 4), 256>>>(qb, kb, nullptr, scb,
        Pn, Pn, EMBn, EMBn, EMBn, Pn, 380L*768, 380L*768, 380L*380, SCALE_EMB);
    pair_softmax_k<<<BPn, 128>>>(scb, vis);
    sgemm_k<false,false,false><<<dim3(12, 6, 4), 256>>>(scb, vb, nullptr, atto,
        Pn, EMBn, Pn, Pn, EMBn, EMBn, 380L*380, 380L*768, 380L*768, 1.f);
    // 10) classifier head
    catfeat_k<<<BPn, 256>>>(hs_t, ts_t, pair1, atto, catf);
    sgemm_k<false,true,true><<<dim3(12, 24, 1), 256>>>(catf, Wp1, bp1, h1,
        BPn, EMBn, 2304, 2304, EMBn, EMBn, 0, 0, 0, 1.f);
    sgemm_k<false,true,false><<<dim3(2, 24, 1), 256>>>(h1, Wp2, bp2, out,
        BPn, NCLSn, EMBn, EMBn, NCLSn, NCLSn, 0, 0, 0, 1.f);
}

// round 3
// speedup vs baseline: 2.0924x; 2.0924x over previous
#include <cuda_runtime.h>
#include <stdint.h>
#include <math.h>

// ---------------- problem constants ----------------
#define Bn   4
#define Cn   512
#define Hn   768
#define NHn  12
#define NEn  20
#define MMn  23
#define Pn   380
#define BPn  1520
#define QSn  128
#define EMBn 768
#define NBn  12
#define BLKn 64
#define NCLSn 97
#define POSn 128

static __device__ __constant__ float kNEG = -10000.0f;
#define SCALE_EMB 0.03608439182435161f   // 1/sqrt(768)

// ---------------- scratch ----------------
#define OFF_ENT_EMB 0UL
#define OFF_ENT_ATT (OFF_ENT_EMB + 1840UL*768)
#define OFF_ENT_Q   (OFF_ENT_ATT + 960UL*512)
#define OFF_HT_ATT  (OFF_ENT_Q   + 1840UL*128)
#define OFF_RS      (OFF_HT_ATT  + 1520UL*512)
#define OFF_HTQ     (OFF_RS      + 1520UL*768)
#define OFF_HS_ATT  (OFF_HTQ     + 1520UL*128)
#define OFF_TS_ATT  (OFF_HS_ATT  + 1520UL*768)
#define OFF_CAT_H   (OFF_TS_ATT  + 1520UL*768)
#define OFF_CAT_T   (OFF_CAT_H   + 1520UL*1536)
#define OFF_HS      (OFF_CAT_T   + 1520UL*1536)
#define OFF_TS      (OFF_HS      + 1520UL*768)
#define OFF_PAIRG   (OFF_TS      + 1520UL*768)
#define OFF_CATPP   (OFF_PAIRG   + 1520UL*768)
#define OFF_PAIR1   (OFF_CATPP   + 1520UL*1024)
#define OFF_QB      (OFF_PAIR1   + 1520UL*768)
#define OFF_KB      (OFF_QB      + 1520UL*768)
#define OFF_VB      (OFF_KB      + 1520UL*768)
#define OFF_SC      (OFF_VB      + 1520UL*768)
#define OFF_ATTO    (OFF_SC      + 4UL*380*380)
#define OFF_CATF    (OFF_ATTO    + 1520UL*768)
#define OFF_H1      (OFF_CATF    + 1520UL*2304)
#define SCRATCH_TOTAL (OFF_H1    + 1520UL*768)

__device__ float g_scratch[SCRATCH_TOTAL];

// ---------------- tf32 mma helpers ----------------
__device__ __forceinline__ uint32_t f2tf32(float x) {
    uint32_t r; asm("cvt.rna.tf32.f32 %0, %1;" : "=r"(r) : "f"(x)); return r;
}
__device__ __forceinline__ void mma_tf32(float* c, const uint32_t* a, const uint32_t* b) {
    asm volatile("mma.sync.aligned.m16n8k8.row.col.f32.tf32.tf32.f32 "
        "{%0,%1,%2,%3}, {%4,%5,%6,%7}, {%8,%9}, {%0,%1,%2,%3};"
        : "+f"(c[0]), "+f"(c[1]), "+f"(c[2]), "+f"(c[3])
        : "r"(a[0]), "r"(a[1]), "r"(a[2]), "r"(a[3]), "r"(b[0]), "r"(b[1]));
}

// ---------------- generic tf32 tensor-core GEMM ----------------
// C = act(alpha*A@B(+bias)); A: MxK row-major; B: KxN (or NxK if TRANSB).
// Block tile 128x64, BK=16, 8 warps of 32x32.
#define GT_BM 128
#define GT_BN 64
#define GT_BK 16

template<bool TRANSB, bool BIAS, bool TANH>
__global__ __launch_bounds__(256)
void gemm_tc(const float* __restrict__ A, const float* __restrict__ Bm,
             const float* __restrict__ bias, float* __restrict__ C,
             int M, int N, int K, int lda, int ldb, int ldc,
             long sA, long sB, long sC, float alpha)
{
    __shared__ uint32_t As[GT_BK][GT_BM + 8];   // [k][m]
    __shared__ uint32_t Bs[GT_BK][GT_BN + 8];   // [k][n]
    const int tid = threadIdx.x;
    const int wid = tid >> 5, lane = tid & 31;
    const int gid = lane >> 2, tig = lane & 3;
    const int m0 = blockIdx.y * GT_BM, n0 = blockIdx.x * GT_BN;
    A  += (long)blockIdx.z * sA;
    Bm += (long)blockIdx.z * sB;
    C  += (long)blockIdx.z * sC;
    const int wm0 = (wid & 3) * 32;
    const int wn0 = (wid >> 2) * 32;
    float acc[2][4][4] = {};

    const int ar = tid >> 1, ac = (tid & 1) * 8;
    const int br = tid >> 4, bc = (tid & 15) * 4;
    const int tbn = tid >> 2, tbk = (tid & 3) * 4;
    const bool mok = (m0 + ar) < M;
    const bool ldb_al = ((ldb & 3) == 0);

    for (int k0 = 0; k0 < K; k0 += GT_BK) {
        // ---- A tile -> As[k][m] (tf32) ----
        {
            const float* Ap = A + (long)(m0 + ar) * lda + k0 + ac;
            if (mok && (k0 + GT_BK) <= K) {
                float4 v0 = *(const float4*)Ap;
                float4 v1 = *(const float4*)(Ap + 4);
                As[ac + 0][ar] = f2tf32(v0.x); As[ac + 1][ar] = f2tf32(v0.y);
                As[ac + 2][ar] = f2tf32(v0.z); As[ac + 3][ar] = f2tf32(v0.w);
                As[ac + 4][ar] = f2tf32(v1.x); As[ac + 5][ar] = f2tf32(v1.y);
                As[ac + 6][ar] = f2tf32(v1.z); As[ac + 7][ar] = f2tf32(v1.w);
            } else {
                #pragma unroll
                for (int i = 0; i < 8; ++i) {
                    float v = (mok && (k0 + ac + i) < K) ? Ap[i] : 0.f;
                    As[ac + i][ar] = f2tf32(v);
                }
            }
        }
        // ---- B tile -> Bs[k][n] (tf32) ----
        if (!TRANSB) {
            const bool kok = (k0 + br) < K;
            const float* Bp = Bm + (long)(k0 + br) * ldb + n0 + bc;
            if (kok && ldb_al && (n0 + bc + 3) < N) {
                float4 v = *(const float4*)Bp;
                uint4 u; u.x = f2tf32(v.x); u.y = f2tf32(v.y);
                u.z = f2tf32(v.z); u.w = f2tf32(v.w);
                *(uint4*)&Bs[br][bc] = u;
            } else {
                #pragma unroll
                for (int i = 0; i < 4; ++i) {
                    float v = (kok && (n0 + bc + i) < N) ? Bp[i] : 0.f;
                    Bs[br][bc + i] = f2tf32(v);
                }
            }
        } else {
            const bool nok = (n0 + tbn) < N;
            const float* Bp = Bm + (long)(n0 + tbn) * ldb + k0 + tbk;
            if (nok && ldb_al && (k0 + tbk + 3) < K) {
                float4 v = *(const float4*)Bp;
                Bs[tbk + 0][tbn] = f2tf32(v.x);
                Bs[tbk + 1][tbn] = f2tf32(v.y);
                Bs[tbk + 2][tbn] = f2tf32(v.z);
                Bs[tbk + 3][tbn] = f2tf32(v.w);
            } else {
                #pragma unroll
                for (int i = 0; i < 4; ++i) {
                    float v = (nok && (k0 + tbk + i) < K) ? Bp[i] : 0.f;
                    Bs[tbk + i][tbn] = f2tf32(v);
                }
            }
        }
        __syncthreads();
        #pragma unroll
        for (int kk = 0; kk < GT_BK; kk += 8) {
            uint32_t af[2][4], bf[4][2];
            #pragma unroll
            for (int mf = 0; mf < 2; ++mf) {
                const int r = wm0 + mf * 16;
                af[mf][0] = As[kk + tig][r + gid];
                af[mf][1] = As[kk + tig][r + 8 + gid];
                af[mf][2] = As[kk + tig + 4][r + gid];
                af[mf][3] = As[kk + tig + 4][r + 8 + gid];
            }
            #pragma unroll
            for (int nf = 0; nf < 4; ++nf) {
                const int c = wn0 + nf * 8 + gid;
                bf[nf][0] = Bs[kk + tig][c];
                bf[nf][1] = Bs[kk + tig + 4][c];
            }
            #pragma unroll
            for (int mf = 0; mf < 2; ++mf)
                #pragma unroll
                for (int nf = 0; nf < 4; ++nf)
                    mma_tf32(acc[mf][nf], af[mf], bf[nf]);
        }
        __syncthreads();
    }
    // ---- epilogue ----
    #pragma unroll
    for (int mf = 0; mf < 2; ++mf) {
        #pragma unroll
        for (int nf = 0; nf < 4; ++nf) {
            const int r = m0 + wm0 + mf * 16 + gid;
            const int c = n0 + wn0 + nf * 8 + tig * 2;
            #pragma unroll
            for (int half = 0; half < 2; ++half) {
                const int rr = r + half * 8;
                if (rr >= M) continue;
                #pragma unroll
                for (int j = 0; j < 2; ++j) {
                    const int cc = c + j;
                    if (cc >= N) continue;
                    float v = acc[mf][nf][half * 2 + j] * alpha;
                    if (BIAS) v += bias[cc];
                    if (TANH) v = tanhf(v);
                    C[(long)rr * ldc + cc] = v;
                }
            }
        }
    }
}

// ---------------- implicit bilinear GEMM (tf32 tensor cores) ----------------
// C[m,n] = sum_{nb,i,j} Hs[m,nb*64+i]*Ts[m,nb*64+j]*W[(nb*4096+i*64+j), n] + bias[n]
#define BL_SMEM (2*128*68*4 + 64*72*4)
__global__ __launch_bounds__(256)
void bilinear_tc(const float* __restrict__ Hs, const float* __restrict__ Ts,
                 const float* __restrict__ W, const float* __restrict__ bias,
                 float* __restrict__ C, int M)
{
    extern __shared__ char smraw[];
    float* bh = (float*)smraw;                    // [128][68]
    float* bt = bh + 128 * 68;                    // [128][68]
    uint32_t* Ws = (uint32_t*)(bt + 128 * 68);    // [64][72] tf32
    const int tid = threadIdx.x;
    const int wid = tid >> 5, lane = tid & 31;
    const int gid = lane >> 2, tig = lane & 3;
    const int m0 = blockIdx.y * 128, n0 = blockIdx.x * 64;
    const int wm0 = (wid & 3) * 32, wn0 = (wid >> 2) * 32;
    float acc[2][4][4] = {};

    const int lr = tid >> 1, lc = (tid & 1) * 32;
    const bool lok = (m0 + lr) < M;
    const int jr = tid >> 2, jc = (tid & 3) * 16;

    for (int nb = 0; nb < NBn; ++nb) {
        __syncthreads();
        {
            const float* hp = Hs + (long)(m0 + lr) * 768 + nb * 64 + lc;
            const float* tp = Ts + (long)(m0 + lr) * 768 + nb * 64 + lc;
            #pragma unroll
            for (int q = 0; q < 8; ++q) {
                float4 hv = lok ? *(const float4*)(hp + 4 * q) : make_float4(0, 0, 0, 0);
                float4 tv = lok ? *(const float4*)(tp + 4 * q) : make_float4(0, 0, 0, 0);
                *(float4*)&bh[lr * 68 + lc + 4 * q] = hv;
                *(float4*)&bt[lr * 68 + lc + 4 * q] = tv;
            }
        }
        for (int i = 0; i < 64; ++i) {
            __syncthreads();
            {
                const float* wp = W + ((long)(nb * 4096 + i * 64 + jr)) * 768 + n0 + jc;
                #pragma unroll
                for (int q = 0; q < 4; ++q) {
                    float4 wv = *(const float4*)(wp + 4 * q);
                    uint4 uv;
                    uv.x = f2tf32(wv.x); uv.y = f2tf32(wv.y);
                    uv.z = f2tf32(wv.z); uv.w = f2tf32(wv.w);
                    *(uint4*)&Ws[jr * 72 + jc + 4 * q] = uv;
                }
            }
            __syncthreads();
            float bhv[2][2];
            #pragma unroll
            for (int mf = 0; mf < 2; ++mf) {
                bhv[mf][0] = bh[(wm0 + mf * 16 + gid) * 68 + i];
                bhv[mf][1] = bh[(wm0 + mf * 16 + 8 + gid) * 68 + i];
            }
            #pragma unroll
            for (int j0 = 0; j0 < 64; j0 += 8) {
                uint32_t bf[4][2];
                #pragma unroll
                for (int nf = 0; nf < 4; ++nf) {
                    bf[nf][0] = Ws[(j0 + tig) * 72 + wn0 + nf * 8 + gid];
                    bf[nf][1] = Ws[(j0 + tig + 4) * 72 + wn0 + nf * 8 + gid];
                }
                #pragma unroll
                for (int mf = 0; mf < 2; ++mf) {
                    const int r0 = wm0 + mf * 16;
                    uint32_t af[4];
                    af[0] = f2tf32(bhv[mf][0] * bt[(r0 + gid) * 68 + j0 + tig]);
                    af[1] = f2tf32(bhv[mf][1] * bt[(r0 + 8 + gid) * 68 + j0 + tig]);
                    af[2] = f2tf32(bhv[mf][0] * bt[(r0 + gid) * 68 + j0 + tig + 4]);
                    af[3] = f2tf32(bhv[mf][1] * bt[(r0 + 8 + gid) * 68 + j0 + tig + 4]);
                    #pragma unroll
                    for (int nf = 0; nf < 4; ++nf)
                        mma_tf32(acc[mf][nf], af, bf[nf]);
                }
            }
        }
    }
    #pragma unroll
    for (int mf = 0; mf < 2; ++mf) {
        #pragma unroll
        for (int nf = 0; nf < 4; ++nf) {
            const int r = m0 + wm0 + mf * 16 + gid;
            const int c = n0 + wn0 + nf * 8 + tig * 2;
            if (r < M) {
                C[(long)r * 768 + c]     = acc[mf][nf][0] + bias[c];
                C[(long)r * 768 + c + 1] = acc[mf][nf][1] + bias[c + 1];
            }
            if (r + 8 < M) {
                C[(long)(r + 8) * 768 + c]     = acc[mf][nf][2] + bias[c];
                C[(long)(r + 8) * 768 + c + 1] = acc[mf][nf][3] + bias[c + 1];
            }
        }
    }
}

// ---------------- small fused kernels ----------------
__global__ void ent_emb_k(const float* __restrict__ seq, const int* __restrict__ midx,
                          const float* __restrict__ mmask, float* __restrict__ ent_emb)
{
    const int blk = blockIdx.x;
    const int b = blk / (MMn * NEn);
    const int idx = midx[blk];
    const float mask = mmask[blk];
    const float* src = seq + ((long)b * Cn + idx) * Hn;
    float* dst = ent_emb + (long)blk * Hn;
    for (int h = threadIdx.x; h < Hn; h += 256) dst[h] = mask * src[h];
}

__global__ void ent_att_k(const float* __restrict__ att, const int* __restrict__ midx,
                          const float* __restrict__ mmask, float* __restrict__ ent_att)
{
    const int blk = blockIdx.x;
    const int nh = blk % NHn;
    const int e  = (blk / NHn) % NEn;
    const int b  = blk / (NHn * NEn);
    const int c  = threadIdx.x;
    const int* mi = midx + (b * NEn + e) * MMn;
    const float* mk = mmask + (b * NEn + e) * MMn;
    float cnt = 0.f, s = 0.f;
    for (int m = 0; m < MMn; ++m) {
        const float w = mk[m];
        cnt += w;
        s += w * att[(((long)b * NHn + nh) * Cn + mi[m]) * Cn + c];
    }
    ent_att[(long)blk * Cn + c] = s / cnt;
}

__global__ void ht_att_k(const float* __restrict__ ent_att, const int* __restrict__ hts,
                         float* __restrict__ ht_att)
{
    const int bp = blockIdx.x;
    const int b = bp / Pn;
    const int hi = hts[bp * 2], ti = hts[bp * 2 + 1];
    const int c = threadIdx.x;
    const float* ha = ent_att + (long)(b * NEn + hi) * NHn * Cn;
    const float* ta = ent_att + (long)(b * NEn + ti) * NHn * Cn;
    float v = 0.f;
    #pragma unroll
    for (int nh = 0; nh < NHn; ++nh) v += ha[nh * Cn + c] * ta[nh * Cn + c];
    v *= (1.f / 12.f);
    __shared__ float red[512];
    red[c] = v; __syncthreads();
    for (int s = 256; s > 0; s >>= 1) { if (c < s) red[c] += red[c + s]; __syncthreads(); }
    ht_att[(long)bp * Cn + c] = v / (red[0] + 1e-5f);
}

__global__ void pool_attn_k(const float* __restrict__ htq, const float* __restrict__ ent_q,
                            const float* __restrict__ ent_emb, const float* __restrict__ mmask,
                            const int* __restrict__ hts, float* __restrict__ hs_att,
                            float* __restrict__ ts_att)
{
    const int bp = blockIdx.x;
    const int side = blockIdx.y;
    const int b = bp / Pn;
    const int e = hts[bp * 2 + side];
    __shared__ float qs[QSn];
    __shared__ float gs[MMn];
    const int tid = threadIdx.x;
    if (tid < QSn) qs[tid] = htq[(long)bp * QSn + tid];
    __syncthreads();
    if (tid < MMn) {
        const float* eq = ent_q + ((long)(b * NEn + e) * MMn + tid) * QSn;
        float d = 0.f;
        for (int i = 0; i < QSn; ++i) d += qs[i] * eq[i];
        const float mk = mmask[(b * NEn + e) * MMn + tid];
        gs[tid] = (mk > 0.f) ? d * SCALE_EMB : kNEG;
    }
    __syncthreads();
    float mx = -1e30f;
    for (int m = 0; m < MMn; ++m) mx = fmaxf(mx, gs[m]);
    float w[MMn]; float ssum = 0.f;
    for (int m = 0; m < MMn; ++m) { w[m] = expf(gs[m] - mx); ssum += w[m]; }
    const float inv = 1.f / ssum;
    const float* emb = ent_emb + (long)(b * NEn + e) * MMn * Hn;
    float* out = (side ? ts_att : hs_att) + (long)bp * Hn;
    for (int h = tid; h < Hn; h += 256) {
        float acc2 = 0.f;
        for (int m = 0; m < MMn; ++m) acc2 += w[m] * emb[m * Hn + h];
        out[h] = acc2 * inv;
    }
}

__global__ void cat2_k(const float* __restrict__ hs_att, const float* __restrict__ ts_att,
                       const float* __restrict__ rs, float* __restrict__ cat_h,
                       float* __restrict__ cat_t)
{
    const long r = blockIdx.x;
    for (int h = threadIdx.x; h < Hn; h += 256) {
        const float rv = rs[r * Hn + h];
        cat_h[r * 1536 + h]       = hs_att[r * Hn + h];
        cat_h[r * 1536 + 768 + h] = rv;
        cat_t[r * 1536 + h]       = ts_att[r * Hn + h];
        cat_t[r * 1536 + 768 + h] = rv;
    }
}

__global__ void catpp_k(const float* __restrict__ pairg, const float* __restrict__ pos_emb,
                        const int* __restrict__ hts, float* __restrict__ catpp)
{
    const long r = blockIdx.x;
    const int hi = hts[r * 2], ti = hts[r * 2 + 1];
    if (threadIdx.x < POSn) {
        catpp[r * 1024 + threadIdx.x]       = pos_emb[hi * POSn + threadIdx.x];
        catpp[r * 1024 + 896 + threadIdx.x] = pos_emb[ti * POSn + threadIdx.x];
    }
    for (int h = threadIdx.x; h < Hn; h += 256)
        catpp[r * 1024 + 128 + h] = pairg[r * Hn + h];
}

__global__ void pair_softmax_k(float* __restrict__ sc, const float* __restrict__ vis)
{
    const long bp = blockIdx.x;
    float* row = sc + bp * Pn;
    const float* vr = vis + bp * Pn;
    const int tid = threadIdx.x;
    __shared__ float red[128];
    float mx = -1e30f;
    for (int q = tid; q < Pn; q += 128) {
        const float v = (vr[q] > 0.f) ? row[q] : kNEG;
        mx = fmaxf(mx, v);
    }
    red[tid] = mx; __syncthreads();
    for (int s = 64; s > 0; s >>= 1) { if (tid < s) red[tid] = fmaxf(red[tid], red[tid + s]); __syncthreads(); }
    mx = red[0]; __syncthreads();
    float sum = 0.f;
    for (int q = tid; q < Pn; q += 128) {
        const float v = (vr[q] > 0.f) ? row[q] : kNEG;
        sum += expf(v - mx);
    }
    red[tid] = sum; __syncthreads();
    for (int s = 64; s > 0; s >>= 1) { if (tid < s) red[tid] += red[tid + s]; __syncthreads(); }
    const float inv = 1.f / red[0];
    for (int q = tid; q < Pn; q += 128) {
        const float v = (vr[q] > 0.f) ? row[q] : kNEG;
        row[q] = expf(v - mx) * inv;
    }
}

__global__ void catfeat_k(const float* __restrict__ hs, const float* __restrict__ ts,
                          const float* __restrict__ pair1, const float* __restrict__ atto,
                          float* __restrict__ catf)
{
    const long r = blockIdx.x;
    for (int h = threadIdx.x; h < Hn; h += 256) {
        catf[r * 2304 + h]        = hs[r * Hn + h];
        catf[r * 2304 + 768 + h]  = ts[r * Hn + h];
        catf[r * 2304 + 1536 + h] = pair1[r * Hn + h] + atto[r * Hn + h];
    }
}

// ---------------- launcher ----------------
extern "C" void kernel_launch(void* const* d_in, const int* in_sizes, int n_in,
                              void* d_out, int out_size)
{
    (void)in_sizes; (void)n_in; (void)out_size;
    const float* seq   = (const float*)d_in[0];
    const float* att   = (const float*)d_in[1];
    const int*   midx  = (const int*)  d_in[2];
    const float* mmask = (const float*)d_in[3];
    const int*   hts   = (const int*)  d_in[4];
    const float* vis   = (const float*)d_in[5];
    const float* Wcq = (const float*)d_in[6],  *bcq = (const float*)d_in[7];
    const float* Weq = (const float*)d_in[8],  *beq = (const float*)d_in[9];
    const float* Whe = (const float*)d_in[10], *bhe = (const float*)d_in[11];
    const float* Wte = (const float*)d_in[12], *bte = (const float*)d_in[13];
    const float* Wbl = (const float*)d_in[14], *bbl = (const float*)d_in[15];
    const float* Wpp = (const float*)d_in[16], *bpp = (const float*)d_in[17];
    const float* Wgq = (const float*)d_in[18];
    const float* Wgk = (const float*)d_in[19];
    const float* Wgv = (const float*)d_in[20];
    const float* Wp1 = (const float*)d_in[21], *bp1 = (const float*)d_in[22];
    const float* Wp2 = (const float*)d_in[23], *bp2 = (const float*)d_in[24];
    const float* pos = (const float*)d_in[25];
    float* out = (float*)d_out;

    float* base = nullptr;
    cudaGetSymbolAddress((void**)&base, g_scratch);
    float* ent_emb = base + OFF_ENT_EMB;
    float* ent_att = base + OFF_ENT_ATT;
    float* ent_q   = base + OFF_ENT_Q;
    float* ht_att  = base + OFF_HT_ATT;
    float* rs      = base + OFF_RS;
    float* htqb    = base + OFF_HTQ;
    float* hs_att  = base + OFF_HS_ATT;
    float* ts_att  = base + OFF_TS_ATT;
    float* cat_h   = base + OFF_CAT_H;
    float* cat_t   = base + OFF_CAT_T;
    float* hs_t    = base + OFF_HS;
    float* ts_t    = base + OFF_TS;
    float* pairg   = base + OFF_PAIRG;
    float* catpp   = base + OFF_CATPP;
    float* pair1   = base + OFF_PAIR1;
    float* qb      = base + OFF_QB;
    float* kb      = base + OFF_KB;
    float* vb      = base + OFF_VB;
    float* scb     = base + OFF_SC;
    float* atto    = base + OFF_ATTO;
    float* catf    = base + OFF_CATF;
    float* h1      = base + OFF_H1;

    cudaFuncSetAttribute(bilinear_tc, cudaFuncAttributeMaxDynamicSharedMemorySize, BL_SMEM);

    // 1) entity gathers
    ent_emb_k<<<Bn * NEn * MMn, 256>>>(seq, midx, mmask, ent_emb);
    ent_att_k<<<Bn * NEn * NHn, 512>>>(att, midx, mmask, ent_att);
    // 2) pair context attention
    ht_att_k<<<BPn, 512>>>(ent_att, hts, ht_att);
    // 3) rs = ht_att @ seq (batched)
    gemm_tc<false,false,false><<<dim3(12, 3, 4), 256>>>(ht_att, seq, nullptr, rs,
        Pn, Hn, Cn, Cn, Hn, Hn, 380L*512, 512L*768, 380L*768, 1.f);
    // 4) htq, ent_q
    gemm_tc<false,true,false><<<dim3(2, 12, 1), 256>>>(rs, Wcq, bcq, htqb,
        BPn, QSn, Hn, Hn, QSn, QSn, 0, 0, 0, 1.f);
    gemm_tc<false,true,false><<<dim3(2, 15, 1), 256>>>(ent_emb, Weq, beq, ent_q,
        1840, QSn, Hn, Hn, QSn, QSn, 0, 0, 0, 1.f);
    // 5) mention-pool softmax
    pool_attn_k<<<dim3(BPn, 2), 256>>>(htqb, ent_q, ent_emb, mmask, hts, hs_att, ts_att);
    // 6) hs/ts projections
    cat2_k<<<BPn, 256>>>(hs_att, ts_att, rs, cat_h, cat_t);
    gemm_tc<false,true,true><<<dim3(12, 12, 1), 256>>>(cat_h, Whe, bhe, hs_t,
        BPn, EMBn, 1536, 1536, EMBn, EMBn, 0, 0, 0, 1.f);
    gemm_tc<false,true,true><<<dim3(12, 12, 1), 256>>>(cat_t, Wte, bte, ts_t,
        BPn, EMBn, 1536, 1536, EMBn, EMBn, 0, 0, 0, 1.f);
    // 7) grouped bilinear (implicit GEMM, tensor cores)
    bilinear_tc<<<dim3(12, 12), 256, BL_SMEM>>>(hs_t, ts_t, Wbl, bbl, pairg, BPn);
    // 8) pos concat + Wpp
    catpp_k<<<BPn, 256>>>(pairg, pos, hts, catpp);
    gemm_tc<false,true,true><<<dim3(12, 12, 1), 256>>>(catpp, Wpp, bpp, pair1,
        BPn, EMBn, 1024, 1024, EMBn, EMBn, 0, 0, 0, 1.f);
    // 9) pair-graph attention
    gemm_tc<false,false,false><<<dim3(12, 12, 1), 256>>>(pair1, Wgq, nullptr, qb,
        BPn, EMBn, EMBn, EMBn, EMBn, EMBn, 0, 0, 0, 1.f);
    gemm_tc<false,false,false><<<dim3(12, 12, 1), 256>>>(pair1, Wgk, nullptr, kb,
        BPn, EMBn, EMBn, EMBn, EMBn, EMBn, 0, 0, 0, 1.f);
    gemm_tc<false,false,false><<<dim3(12, 12, 1), 256>>>(pair1, Wgv, nullptr, vb,
        BPn, EMBn, EMBn, EMBn, EMBn, EMBn, 0, 0, 0, 1.f);
    gemm_tc<true,false,false><<<dim3(6, 3, 4), 256>>>(qb, kb, nullptr, scb,
        Pn, Pn, EMBn, EMBn, EMBn, Pn, 380L*768, 380L*768, 380L*380, SCALE_EMB);
    pair_softmax_k<<<BPn, 128>>>(scb, vis);
    gemm_tc<false,false,false><<<dim3(12, 3, 4), 256>>>(scb, vb, nullptr, atto,
        Pn, EMBn, Pn, Pn, EMBn, EMBn, 380L*380, 380L*768, 380L*768, 1.f);
    // 10) classifier head
    catfeat_k<<<BPn, 256>>>(hs_t, ts_t, pair1, atto, catf);
    gemm_tc<false,true,true><<<dim3(12, 12, 1), 256>>>(catf, Wp1, bp1, h1,
        BPn, EMBn, 2304, 2304, EMBn, EMBn, 0, 0, 0, 1.f);
    gemm_tc<false,true,false><<<dim3(2, 12, 1), 256>>>(h1, Wp2, bp2, out,
        BPn, NCLSn, EMBn, EMBn, NCLSn, NCLSn, 0, 0, 0, 1.f);
}

// round 4
// speedup vs baseline: 3.1045x; 1.4837x over previous
#include <cuda_runtime.h>
#include <stdint.h>
#include <math.h>

// ---------------- problem constants ----------------
#define Bn   4
#define Cn   512
#define Hn   768
#define NHn  12
#define NEn  20
#define MMn  23
#define Pn   380
#define BPn  1520
#define QSn  128
#define EMBn 768
#define NBn  12
#define BLKn 64
#define NCLSn 97
#define POSn 128

static __device__ __constant__ float kNEG = -10000.0f;
#define SCALE_EMB 0.03608439182435161f   // 1/sqrt(768)

// ---------------- scratch ----------------
#define OFF_ENT_EMB 0UL
#define OFF_ENT_ATT (OFF_ENT_EMB + 1840UL*768)
#define OFF_ENT_Q   (OFF_ENT_ATT + 960UL*512)
#define OFF_HT_ATT  (OFF_ENT_Q   + 1840UL*128)
#define OFF_RS      (OFF_HT_ATT  + 1520UL*512)
#define OFF_HTQ     (OFF_RS      + 1520UL*768)
#define OFF_HS_ATT  (OFF_HTQ     + 1520UL*128)
#define OFF_TS_ATT  (OFF_HS_ATT  + 1520UL*768)
#define OFF_CAT_H   (OFF_TS_ATT  + 1520UL*768)
#define OFF_CAT_T   (OFF_CAT_H   + 1520UL*1536)
#define OFF_HS      (OFF_CAT_T   + 1520UL*1536)
#define OFF_TS      (OFF_HS      + 1520UL*768)
#define OFF_PAIRG   (OFF_TS      + 1520UL*768)
#define OFF_CATPP   (OFF_PAIRG   + 1520UL*768)
#define OFF_PAIR1   (OFF_CATPP   + 1520UL*1024)
#define OFF_QB      (OFF_PAIR1   + 1520UL*768)
#define OFF_KB      (OFF_QB      + 1520UL*768)
#define OFF_VB      (OFF_KB      + 1520UL*768)
#define OFF_SC      (OFF_VB      + 1520UL*768)
#define OFF_ATTO    (OFF_SC      + 4UL*380*380)
#define OFF_CATF    (OFF_ATTO    + 1520UL*768)
#define OFF_H1      (OFF_CATF    + 1520UL*2304)
#define SCRATCH_TOTAL (OFF_H1    + 1520UL*768)

__device__ float g_scratch[SCRATCH_TOTAL];

// ---------------- tf32 mma helpers ----------------
__device__ __forceinline__ uint32_t f2tf32(float x) {
    uint32_t r; asm("cvt.rna.tf32.f32 %0, %1;" : "=r"(r) : "f"(x)); return r;
}
__device__ __forceinline__ void mma_tf32(float* c, const uint32_t* a, const uint32_t* b) {
    asm volatile("mma.sync.aligned.m16n8k8.row.col.f32.tf32.tf32.f32 "
        "{%0,%1,%2,%3}, {%4,%5,%6,%7}, {%8,%9}, {%0,%1,%2,%3};"
        : "+f"(c[0]), "+f"(c[1]), "+f"(c[2]), "+f"(c[3])
        : "r"(a[0]), "r"(a[1]), "r"(a[2]), "r"(a[3]), "r"(b[0]), "r"(b[1]));
}

// ---------------- generic tf32 tensor-core GEMM (2-stage pipelined) ----------------
// C = act(alpha*A@B(+bias)); A: MxK row-major; B: KxN (or NxK if TRANSB).
#define GT_BM 128
#define GT_BN 64
#define GT_BK 16

template<bool TRANSB, bool BIAS, bool TANH>
__global__ __launch_bounds__(256)
void gemm_tc(const float* __restrict__ A, const float* __restrict__ Bm,
             const float* __restrict__ bias, float* __restrict__ C,
             int M, int N, int K, int lda, int ldb, int ldc,
             long sA, long sB, long sC, float alpha)
{
    __shared__ uint32_t As[2][GT_BK][GT_BM + 8];   // [stage][k][m]
    __shared__ uint32_t Bs[2][GT_BK][GT_BN + 8];   // [stage][k][n]
    const int tid = threadIdx.x;
    const int wid = tid >> 5, lane = tid & 31;
    const int gid = lane >> 2, tig = lane & 3;
    const int m0 = blockIdx.y * GT_BM, n0 = blockIdx.x * GT_BN;
    A  += (long)blockIdx.z * sA;
    Bm += (long)blockIdx.z * sB;
    C  += (long)blockIdx.z * sC;
    const int wm0 = (wid & 3) * 32;
    const int wn0 = (wid >> 2) * 32;
    float acc[2][4][4] = {};

    const int ar = tid >> 1, ac = (tid & 1) * 8;
    const int br = tid >> 4, bc = (tid & 15) * 4;
    const int tbn = tid >> 2, tbk = (tid & 3) * 4;
    const bool mok = (m0 + ar) < M;
    const bool ldb_al = ((ldb & 3) == 0);
    float aP[8], bP[4];

#define LOAD_A(k0_) { \
    const float* Ap = A + (long)(m0 + ar) * lda + (k0_) + ac; \
    if (mok && ((k0_) + GT_BK) <= K) { \
        float4 v0 = *(const float4*)Ap; float4 v1 = *(const float4*)(Ap + 4); \
        aP[0]=v0.x; aP[1]=v0.y; aP[2]=v0.z; aP[3]=v0.w; \
        aP[4]=v1.x; aP[5]=v1.y; aP[6]=v1.z; aP[7]=v1.w; \
    } else { \
        _Pragma("unroll") for (int i_=0;i_<8;++i_) aP[i_] = (mok && ((k0_)+ac+i_)<K) ? Ap[i_] : 0.f; } }

#define STORE_A(st_) { _Pragma("unroll") for (int i_=0;i_<8;++i_) As[st_][ac+i_][ar] = f2tf32(aP[i_]); }

#define LOAD_B(k0_) { if (!TRANSB) { \
    const bool kok = ((k0_) + br) < K; \
    const float* Bp = Bm + (long)((k0_) + br) * ldb + n0 + bc; \
    if (kok && ldb_al && (n0 + bc + 3) < N) { float4 v=*(const float4*)Bp; bP[0]=v.x;bP[1]=v.y;bP[2]=v.z;bP[3]=v.w; } \
    else { _Pragma("unroll") for (int i_=0;i_<4;++i_) bP[i_] = (kok && (n0+bc+i_)<N) ? Bp[i_] : 0.f; } \
  } else { \
    const bool nok = (n0 + tbn) < N; \
    const float* Bp = Bm + (long)(n0 + tbn) * ldb + (k0_) + tbk; \
    if (nok && ldb_al && ((k0_) + tbk + 3) < K) { float4 v=*(const float4*)Bp; bP[0]=v.x;bP[1]=v.y;bP[2]=v.z;bP[3]=v.w; } \
    else { _Pragma("unroll") for (int i_=0;i_<4;++i_) bP[i_] = (nok && ((k0_)+tbk+i_)<K) ? Bp[i_] : 0.f; } } }

#define STORE_B(st_) { if (!TRANSB) { \
    _Pragma("unroll") for (int i_=0;i_<4;++i_) Bs[st_][br][bc+i_] = f2tf32(bP[i_]); \
  } else { \
    _Pragma("unroll") for (int i_=0;i_<4;++i_) Bs[st_][tbk+i_][tbn] = f2tf32(bP[i_]); } }

    LOAD_A(0); LOAD_B(0);
    STORE_A(0); STORE_B(0);
    __syncthreads();
    int st = 0;
    for (int k0 = 0; k0 < K; k0 += GT_BK) {
        const int kn = k0 + GT_BK;
        const bool more = kn < K;
        if (more) { LOAD_A(kn); LOAD_B(kn); }
        #pragma unroll
        for (int kk = 0; kk < GT_BK; kk += 8) {
            uint32_t af[2][4], bf[4][2];
            #pragma unroll
            for (int mf = 0; mf < 2; ++mf) {
                const int r = wm0 + mf * 16;
                af[mf][0] = As[st][kk + tig][r + gid];
                af[mf][1] = As[st][kk + tig][r + 8 + gid];
                af[mf][2] = As[st][kk + tig + 4][r + gid];
                af[mf][3] = As[st][kk + tig + 4][r + 8 + gid];
            }
            #pragma unroll
            for (int nf = 0; nf < 4; ++nf) {
                const int c = wn0 + nf * 8 + gid;
                bf[nf][0] = Bs[st][kk + tig][c];
                bf[nf][1] = Bs[st][kk + tig + 4][c];
            }
            #pragma unroll
            for (int mf = 0; mf < 2; ++mf)
                #pragma unroll
                for (int nf = 0; nf < 4; ++nf)
                    mma_tf32(acc[mf][nf], af[mf], bf[nf]);
        }
        if (more) { STORE_A(st ^ 1); STORE_B(st ^ 1); }
        __syncthreads();
        st ^= 1;
    }
#undef LOAD_A
#undef STORE_A
#undef LOAD_B
#undef STORE_B
    // ---- epilogue ----
    #pragma unroll
    for (int mf = 0; mf < 2; ++mf) {
        #pragma unroll
        for (int nf = 0; nf < 4; ++nf) {
            const int r = m0 + wm0 + mf * 16 + gid;
            const int c = n0 + wn0 + nf * 8 + tig * 2;
            #pragma unroll
            for (int half = 0; half < 2; ++half) {
                const int rr = r + half * 8;
                if (rr >= M) continue;
                #pragma unroll
                for (int j = 0; j < 2; ++j) {
                    const int cc = c + j;
                    if (cc >= N) continue;
                    float v = acc[mf][nf][half * 2 + j] * alpha;
                    if (BIAS) v += bias[cc];
                    if (TANH) v = tanhf(v);
                    C[(long)rr * ldc + cc] = v;
                }
            }
        }
    }
}

// ---------------- implicit bilinear GEMM, factorized (tf32 tensor cores) ----------------
// C[m,n] = sum_{nb,i,j} Hs[m,nb*64+i]*Ts[m,nb*64+j]*W[(nb*4096+i*64+j), n] + bias[n]
// Per (nb,i): A-tile = diag(bh[:,i]) @ BT, BT constant across i within nb.
// bt fragments cached in registers per nb; inner step: D = BT @ W_t (mma), C += bh[:,i] ∘ D.
#define BL_SMEM ((2*128*68 + 2*64*72) * 4)
__global__ __launch_bounds__(256)
void bilinear_tc(const float* __restrict__ Hs, const float* __restrict__ Ts,
                 const float* __restrict__ W, const float* __restrict__ bias,
                 float* __restrict__ C, int M)
{
    extern __shared__ char smraw[];
    float* bh = (float*)smraw;                    // [128][68]
    float* bt = bh + 128 * 68;                    // [128][68]
    uint32_t* Ws = (uint32_t*)(bt + 128 * 68);    // [2][64][72]
    const int tid = threadIdx.x;
    const int wid = tid >> 5, lane = tid & 31;
    const int gid = lane >> 2, tig = lane & 3;
    const int m0 = blockIdx.y * 128, n0 = blockIdx.x * 64;
    const int wm0 = (wid & 3) * 32, wn0 = (wid >> 2) * 32;
    float acc[2][4][4] = {};
    const int lr = tid >> 1, lc = (tid & 1) * 32;
    const bool lok = (m0 + lr) < M;
    const int jr = tid >> 2, jc = (tid & 3) * 16;
    float wreg[16];
    uint32_t btf[2][8][4];     // cached bt fragments for current nb

#define LOADHT(nb_) { \
    const float* hp = Hs + (long)(m0 + lr) * 768 + (nb_) * 64 + lc; \
    const float* tp = Ts + (long)(m0 + lr) * 768 + (nb_) * 64 + lc; \
    _Pragma("unroll") for (int q_ = 0; q_ < 8; ++q_) { \
        float4 hv = lok ? *(const float4*)(hp + 4 * q_) : make_float4(0, 0, 0, 0); \
        float4 tv = lok ? *(const float4*)(tp + 4 * q_) : make_float4(0, 0, 0, 0); \
        *(float4*)&bh[lr * 68 + lc + 4 * q_] = hv; \
        *(float4*)&bt[lr * 68 + lc + 4 * q_] = tv; } }

#define LOADW(t_) { \
    const float* wp = W + ((long)(t_) * 64 + jr) * 768 + n0 + jc; \
    _Pragma("unroll") for (int q_ = 0; q_ < 4; ++q_) { \
        float4 wv = *(const float4*)(wp + 4 * q_); \
        wreg[4*q_] = wv.x; wreg[4*q_+1] = wv.y; wreg[4*q_+2] = wv.z; wreg[4*q_+3] = wv.w; } }

#define STOREW(st_) { uint32_t* Wd = Ws + (st_) * 4608 + jr * 72 + jc; \
    _Pragma("unroll") for (int q_ = 0; q_ < 16; ++q_) Wd[q_] = f2tf32(wreg[q_]); }

#define CACHEBT() { \
    _Pragma("unroll") for (int mf_ = 0; mf_ < 2; ++mf_) { const int r0_ = wm0 + mf_ * 16; \
        _Pragma("unroll") for (int j0_ = 0; j0_ < 8; ++j0_) { \
            btf[mf_][j0_][0] = f2tf32(bt[(r0_ + gid) * 68 + j0_ * 8 + tig]); \
            btf[mf_][j0_][1] = f2tf32(bt[(r0_ + 8 + gid) * 68 + j0_ * 8 + tig]); \
            btf[mf_][j0_][2] = f2tf32(bt[(r0_ + gid) * 68 + j0_ * 8 + tig + 4]); \
            btf[mf_][j0_][3] = f2tf32(bt[(r0_ + 8 + gid) * 68 + j0_ * 8 + tig + 4]); } } }

    LOADHT(0);
    LOADW(0);
    __syncthreads();
    CACHEBT();
    STOREW(0);
    __syncthreads();
    int st = 0;
    for (int t = 0; t < NBn * 64; ++t) {
        const int tn = t + 1;
        const bool more = tn < NBn * 64;
        if (more) LOADW(tn);
        const int i = t & 63;
        const uint32_t* Wc = Ws + st * 4608;
        float D[2][4][4] = {};
        #pragma unroll
        for (int j0 = 0; j0 < 8; ++j0) {
            uint32_t bf[4][2];
            #pragma unroll
            for (int nf = 0; nf < 4; ++nf) {
                bf[nf][0] = Wc[(j0 * 8 + tig) * 72 + wn0 + nf * 8 + gid];
                bf[nf][1] = Wc[(j0 * 8 + tig + 4) * 72 + wn0 + nf * 8 + gid];
            }
            #pragma unroll
            for (int mf = 0; mf < 2; ++mf)
                #pragma unroll
                for (int nf = 0; nf < 4; ++nf)
                    mma_tf32(D[mf][nf], btf[mf][j0], bf[nf]);
        }
        // C += bh[:, i] ∘ D   (bh kept in exact fp32)
        #pragma unroll
        for (int mf = 0; mf < 2; ++mf) {
            const float b0 = bh[(wm0 + mf * 16 + gid) * 68 + i];
            const float b1 = bh[(wm0 + mf * 16 + 8 + gid) * 68 + i];
            #pragma unroll
            for (int nf = 0; nf < 4; ++nf) {
                acc[mf][nf][0] = fmaf(b0, D[mf][nf][0], acc[mf][nf][0]);
                acc[mf][nf][1] = fmaf(b0, D[mf][nf][1], acc[mf][nf][1]);
                acc[mf][nf][2] = fmaf(b1, D[mf][nf][2], acc[mf][nf][2]);
                acc[mf][nf][3] = fmaf(b1, D[mf][nf][3], acc[mf][nf][3]);
            }
        }
        if (more && (tn & 63) == 0) {
            __syncthreads();           // all reads of bh done
            LOADHT(tn >> 6);
            __syncthreads();           // bh/bt visible
            CACHEBT();
        }
        if (more) STOREW(st ^ 1);
        __syncthreads();
        st ^= 1;
    }
#undef LOADHT
#undef LOADW
#undef STOREW
#undef CACHEBT
    #pragma unroll
    for (int mf = 0; mf < 2; ++mf) {
        #pragma unroll
        for (int nf = 0; nf < 4; ++nf) {
            const int r = m0 + wm0 + mf * 16 + gid;
            const int c = n0 + wn0 + nf * 8 + tig * 2;
            if (r < M) {
                C[(long)r * 768 + c]     = acc[mf][nf][0] + bias[c];
                C[(long)r * 768 + c + 1] = acc[mf][nf][1] + bias[c + 1];
            }
            if (r + 8 < M) {
                C[(long)(r + 8) * 768 + c]     = acc[mf][nf][2] + bias[c];
                C[(long)(r + 8) * 768 + c + 1] = acc[mf][nf][3] + bias[c + 1];
            }
        }
    }
}

// ---------------- small fused kernels ----------------
__global__ void ent_emb_k(const float* __restrict__ seq, const int* __restrict__ midx,
                          const float* __restrict__ mmask, float* __restrict__ ent_emb)
{
    const int blk = blockIdx.x;
    const int b = blk / (MMn * NEn);
    const int idx = midx[blk];
    const float mask = mmask[blk];
    const float* src = seq + ((long)b * Cn + idx) * Hn;
    float* dst = ent_emb + (long)blk * Hn;
    for (int h = threadIdx.x; h < Hn; h += 256) dst[h] = mask * src[h];
}

__global__ void ent_att_k(const float* __restrict__ att, const int* __restrict__ midx,
                          const float* __restrict__ mmask, float* __restrict__ ent_att)
{
    const int blk = blockIdx.x;
    const int nh = blk % NHn;
    const int e  = (blk / NHn) % NEn;
    const int b  = blk / (NHn * NEn);
    const int c  = threadIdx.x;
    const int* mi = midx + (b * NEn + e) * MMn;
    const float* mk = mmask + (b * NEn + e) * MMn;
    float cnt = 0.f, s = 0.f;
    for (int m = 0; m < MMn; ++m) {
        const float w = mk[m];
        cnt += w;
        s += w * att[(((long)b * NHn + nh) * Cn + mi[m]) * Cn + c];
    }
    ent_att[(long)blk * Cn + c] = s / cnt;
}

__global__ void ht_att_k(const float* __restrict__ ent_att, const int* __restrict__ hts,
                         float* __restrict__ ht_att)
{
    const int bp = blockIdx.x;
    const int b = bp / Pn;
    const int hi = hts[bp * 2], ti = hts[bp * 2 + 1];
    const int c = threadIdx.x;
    const float* ha = ent_att + (long)(b * NEn + hi) * NHn * Cn;
    const float* ta = ent_att + (long)(b * NEn + ti) * NHn * Cn;
    float v = 0.f;
    #pragma unroll
    for (int nh = 0; nh < NHn; ++nh) v += ha[nh * Cn + c] * ta[nh * Cn + c];
    v *= (1.f / 12.f);
    __shared__ float red[512];
    red[c] = v; __syncthreads();
    for (int s = 256; s > 0; s >>= 1) { if (c < s) red[c] += red[c + s]; __syncthreads(); }
    ht_att[(long)bp * Cn + c] = v / (red[0] + 1e-5f);
}

__global__ void pool_attn_k(const float* __restrict__ htq, const float* __restrict__ ent_q,
                            const float* __restrict__ ent_emb, const float* __restrict__ mmask,
                            const int* __restrict__ hts, float* __restrict__ hs_att,
                            float* __restrict__ ts_att)
{
    const int bp = blockIdx.x;
    const int side = blockIdx.y;
    const int b = bp / Pn;
    const int e = hts[bp * 2 + side];
    __shared__ float qs[QSn];
    __shared__ float gs[MMn];
    const int tid = threadIdx.x;
    if (tid < QSn) qs[tid] = htq[(long)bp * QSn + tid];
    __syncthreads();
    if (tid < MMn) {
        const float* eq = ent_q + ((long)(b * NEn + e) * MMn + tid) * QSn;
        float d = 0.f;
        for (int i = 0; i < QSn; ++i) d += qs[i] * eq[i];
        const float mk = mmask[(b * NEn + e) * MMn + tid];
        gs[tid] = (mk > 0.f) ? d * SCALE_EMB : kNEG;
    }
    __syncthreads();
    float mx = -1e30f;
    for (int m = 0; m < MMn; ++m) mx = fmaxf(mx, gs[m]);
    float w[MMn]; float ssum = 0.f;
    for (int m = 0; m < MMn; ++m) { w[m] = expf(gs[m] - mx); ssum += w[m]; }
    const float inv = 1.f / ssum;
    const float* emb = ent_emb + (long)(b * NEn + e) * MMn * Hn;
    float* out = (side ? ts_att : hs_att) + (long)bp * Hn;
    for (int h = tid; h < Hn; h += 256) {
        float acc2 = 0.f;
        for (int m = 0; m < MMn; ++m) acc2 += w[m] * emb[m * Hn + h];
        out[h] = acc2 * inv;
    }
}

__global__ void cat2_k(const float* __restrict__ hs_att, const float* __restrict__ ts_att,
                       const float* __restrict__ rs, float* __restrict__ cat_h,
                       float* __restrict__ cat_t)
{
    const long r = blockIdx.x;
    for (int h = threadIdx.x; h < Hn; h += 256) {
        const float rv = rs[r * Hn + h];
        cat_h[r * 1536 + h]       = hs_att[r * Hn + h];
        cat_h[r * 1536 + 768 + h] = rv;
        cat_t[r * 1536 + h]       = ts_att[r * Hn + h];
        cat_t[r * 1536 + 768 + h] = rv;
    }
}

__global__ void catpp_k(const float* __restrict__ pairg, const float* __restrict__ pos_emb,
                        const int* __restrict__ hts, float* __restrict__ catpp)
{
    const long r = blockIdx.x;
    const int hi = hts[r * 2], ti = hts[r * 2 + 1];
    if (threadIdx.x < POSn) {
        catpp[r * 1024 + threadIdx.x]       = pos_emb[hi * POSn + threadIdx.x];
        catpp[r * 1024 + 896 + threadIdx.x] = pos_emb[ti * POSn + threadIdx.x];
    }
    for (int h = threadIdx.x; h < Hn; h += 256)
        catpp[r * 1024 + 128 + h] = pairg[r * Hn + h];
}

__global__ void pair_softmax_k(float* __restrict__ sc, const float* __restrict__ vis)
{
    const long bp = blockIdx.x;
    float* row = sc + bp * Pn;
    const float* vr = vis + bp * Pn;
    const int tid = threadIdx.x;
    __shared__ float red[128];
    float mx = -1e30f;
    for (int q = tid; q < Pn; q += 128) {
        const float v = (vr[q] > 0.f) ? row[q] : kNEG;
        mx = fmaxf(mx, v);
    }
    red[tid] = mx; __syncthreads();
    for (int s = 64; s > 0; s >>= 1) { if (tid < s) red[tid] = fmaxf(red[tid], red[tid + s]); __syncthreads(); }
    mx = red[0]; __syncthreads();
    float sum = 0.f;
    for (int q = tid; q < Pn; q += 128) {
        const float v = (vr[q] > 0.f) ? row[q] : kNEG;
        sum += expf(v - mx);
    }
    red[tid] = sum; __syncthreads();
    for (int s = 64; s > 0; s >>= 1) { if (tid < s) red[tid] += red[tid + s]; __syncthreads(); }
    const float inv = 1.f / red[0];
    for (int q = tid; q < Pn; q += 128) {
        const float v = (vr[q] > 0.f) ? row[q] : kNEG;
        row[q] = expf(v - mx) * inv;
    }
}

__global__ void catfeat_k(const float* __restrict__ hs, const float* __restrict__ ts,
                          const float* __restrict__ pair1, const float* __restrict__ atto,
                          float* __restrict__ catf)
{
    const long r = blockIdx.x;
    for (int h = threadIdx.x; h < Hn; h += 256) {
        catf[r * 2304 + h]        = hs[r * Hn + h];
        catf[r * 2304 + 768 + h]  = ts[r * Hn + h];
        catf[r * 2304 + 1536 + h] = pair1[r * Hn + h] + atto[r * Hn + h];
    }
}

// ---------------- launcher ----------------
extern "C" void kernel_launch(void* const* d_in, const int* in_sizes, int n_in,
                              void* d_out, int out_size)
{
    (void)in_sizes; (void)n_in; (void)out_size;
    const float* seq   = (const float*)d_in[0];
    const float* att   = (const float*)d_in[1];
    const int*   midx  = (const int*)  d_in[2];
    const float* mmask = (const float*)d_in[3];
    const int*   hts   = (const int*)  d_in[4];
    const float* vis   = (const float*)d_in[5];
    const float* Wcq = (const float*)d_in[6],  *bcq = (const float*)d_in[7];
    const float* Weq = (const float*)d_in[8],  *beq = (const float*)d_in[9];
    const float* Whe = (const float*)d_in[10], *bhe = (const float*)d_in[11];
    const float* Wte = (const float*)d_in[12], *bte = (const float*)d_in[13];
    const float* Wbl = (const float*)d_in[14], *bbl = (const float*)d_in[15];
    const float* Wpp = (const float*)d_in[16], *bpp = (const float*)d_in[17];
    const float* Wgq = (const float*)d_in[18];
    const float* Wgk = (const float*)d_in[19];
    const float* Wgv = (const float*)d_in[20];
    const float* Wp1 = (const float*)d_in[21], *bp1 = (const float*)d_in[22];
    const float* Wp2 = (const float*)d_in[23], *bp2 = (const float*)d_in[24];
    const float* pos = (const float*)d_in[25];
    float* out = (float*)d_out;

    float* base = nullptr;
    cudaGetSymbolAddress((void**)&base, g_scratch);
    float* ent_emb = base + OFF_ENT_EMB;
    float* ent_att = base + OFF_ENT_ATT;
    float* ent_q   = base + OFF_ENT_Q;
    float* ht_att  = base + OFF_HT_ATT;
    float* rs      = base + OFF_RS;
    float* htqb    = base + OFF_HTQ;
    float* hs_att  = base + OFF_HS_ATT;
    float* ts_att  = base + OFF_TS_ATT;
    float* cat_h   = base + OFF_CAT_H;
    float* cat_t   = base + OFF_CAT_T;
    float* hs_t    = base + OFF_HS;
    float* ts_t    = base + OFF_TS;
    float* pairg   = base + OFF_PAIRG;
    float* catpp   = base + OFF_CATPP;
    float* pair1   = base + OFF_PAIR1;
    float* qb      = base + OFF_QB;
    float* kb      = base + OFF_KB;
    float* vb      = base + OFF_VB;
    float* scb     = base + OFF_SC;
    float* atto    = base + OFF_ATTO;
    float* catf    = base + OFF_CATF;
    float* h1      = base + OFF_H1;

    cudaFuncSetAttribute(bilinear_tc, cudaFuncAttributeMaxDynamicSharedMemorySize, BL_SMEM);

    // 1) entity gathers
    ent_emb_k<<<Bn * NEn * MMn, 256>>>(seq, midx, mmask, ent_emb);
    ent_att_k<<<Bn * NEn * NHn, 512>>>(att, midx, mmask, ent_att);
    // 2) pair context attention
    ht_att_k<<<BPn, 512>>>(ent_att, hts, ht_att);
    // 3) rs = ht_att @ seq (batched)
    gemm_tc<false,false,false><<<dim3(12, 3, 4), 256>>>(ht_att, seq, nullptr, rs,
        Pn, Hn, Cn, Cn, Hn, Hn, 380L*512, 512L*768, 380L*768, 1.f);
    // 4) htq, ent_q
    gemm_tc<false,true,false><<<dim3(2, 12, 1), 256>>>(rs, Wcq, bcq, htqb,
        BPn, QSn, Hn, Hn, QSn, QSn, 0, 0, 0, 1.f);
    gemm_tc<false,true,false><<<dim3(2, 15, 1), 256>>>(ent_emb, Weq, beq, ent_q,
        1840, QSn, Hn, Hn, QSn, QSn, 0, 0, 0, 1.f);
    // 5) mention-pool softmax
    pool_attn_k<<<dim3(BPn, 2), 256>>>(htqb, ent_q, ent_emb, mmask, hts, hs_att, ts_att);
    // 6) hs/ts projections
    cat2_k<<<BPn, 256>>>(hs_att, ts_att, rs, cat_h, cat_t);
    gemm_tc<false,true,true><<<dim3(12, 12, 1), 256>>>(cat_h, Whe, bhe, hs_t,
        BPn, EMBn, 1536, 1536, EMBn, EMBn, 0, 0, 0, 1.f);
    gemm_tc<false,true,true><<<dim3(12, 12, 1), 256>>>(cat_t, Wte, bte, ts_t,
        BPn, EMBn, 1536, 1536, EMBn, EMBn, 0, 0, 0, 1.f);
    // 7) grouped bilinear (implicit GEMM, tensor cores, factorized)
    bilinear_tc<<<dim3(12, 12), 256, BL_SMEM>>>(hs_t, ts_t, Wbl, bbl, pairg, BPn);
    // 8) pos concat + Wpp
    catpp_k<<<BPn, 256>>>(pairg, pos, hts, catpp);
    gemm_tc<false,true,true><<<dim3(12, 12, 1), 256>>>(catpp, Wpp, bpp, pair1,
        BPn, EMBn, 1024, 1024, EMBn, EMBn, 0, 0, 0, 1.f);
    // 9) pair-graph attention
    gemm_tc<false,false,false><<<dim3(12, 12, 1), 256>>>(pair1, Wgq, nullptr, qb,
        BPn, EMBn, EMBn, EMBn, EMBn, EMBn, 0, 0, 0, 1.f);
    gemm_tc<false,false,false><<<dim3(12, 12, 1), 256>>>(pair1, Wgk, nullptr, kb,
        BPn, EMBn, EMBn, EMBn, EMBn, EMBn, 0, 0, 0, 1.f);
    gemm_tc<false,false,false><<<dim3(12, 12, 1), 256>>>(pair1, Wgv, nullptr, vb,
        BPn, EMBn, EMBn, EMBn, EMBn, EMBn, 0, 0, 0, 1.f);
    gemm_tc<true,false,false><<<dim3(6, 3, 4), 256>>>(qb, kb, nullptr, scb,
        Pn, Pn, EMBn, EMBn, EMBn, Pn, 380L*768, 380L*768, 380L*380, SCALE_EMB);
    pair_softmax_k<<<BPn, 128>>>(scb, vis);
    gemm_tc<false,false,false><<<dim3(12, 3, 4), 256>>>(scb, vb, nullptr, atto,
        Pn, EMBn, Pn, Pn, EMBn, EMBn, 380L*380, 380L*768, 380L*768, 1.f);
    // 10) classifier head
    catfeat_k<<<BPn, 256>>>(hs_t, ts_t, pair1, atto, catf);
    gemm_tc<false,true,true><<<dim3(12, 12, 1), 256>>>(catf, Wp1, bp1, h1,
        BPn, EMBn, 2304, 2304, EMBn, EMBn, 0, 0, 0, 1.f);
    gemm_tc<false,true,false><<<dim3(2, 12, 1), 256>>>(h1, Wp2, bp2, out,
        BPn, NCLSn, EMBn, EMBn, NCLSn, NCLSn, 0, 0, 0, 1.f);
}

// round 5
// speedup vs baseline: 3.2404x; 1.0438x over previous
#include <cuda_runtime.h>
#include <stdint.h>
#include <math.h>

// ---------------- problem constants ----------------
#define Bn   4
#define Cn   512
#define Hn   768
#define NHn  12
#define NEn  20
#define MMn  23
#define Pn   380
#define BPn  1520
#define QSn  128
#define EMBn 768
#define NBn  12
#define BLKn 64
#define NCLSn 97
#define POSn 128

static __device__ __constant__ float kNEG = -10000.0f;
#define SCALE_EMB 0.03608439182435161f   // 1/sqrt(768)

// ---------------- scratch ----------------
#define OFF_ENT_EMB 0UL
#define OFF_ENT_ATT (OFF_ENT_EMB + 1840UL*768)
#define OFF_ENT_Q   (OFF_ENT_ATT + 960UL*512)
#define OFF_HT_ATT  (OFF_ENT_Q   + 1840UL*128)
#define OFF_RS      (OFF_HT_ATT  + 1520UL*512)
#define OFF_HTQ     (OFF_RS      + 1520UL*768)
#define OFF_HS_ATT  (OFF_HTQ     + 1520UL*128)
#define OFF_TS_ATT  (OFF_HS_ATT  + 1520UL*768)
#define OFF_CAT_H   (OFF_TS_ATT  + 1520UL*768)
#define OFF_CAT_T   (OFF_CAT_H   + 1520UL*1536)
#define OFF_HS      (OFF_CAT_T   + 1520UL*1536)
#define OFF_TS      (OFF_HS      + 1520UL*768)
#define OFF_PAIRG   (OFF_TS      + 1520UL*768)
#define OFF_CATPP   (OFF_PAIRG   + 1520UL*768)
#define OFF_PAIR1   (OFF_CATPP   + 1520UL*1024)
#define OFF_QB      (OFF_PAIR1   + 1520UL*768)
#define OFF_KB      (OFF_QB      + 1520UL*768)
#define OFF_VB      (OFF_KB      + 1520UL*768)
#define OFF_SC      (OFF_VB      + 1520UL*768)
#define OFF_ATTO    (OFF_SC      + 4UL*380*380)
#define OFF_CATF    (OFF_ATTO    + 1520UL*768)
#define OFF_H1      (OFF_CATF    + 1520UL*2304)
#define SCRATCH_TOTAL (OFF_H1    + 1520UL*768)

__device__ float g_scratch[SCRATCH_TOTAL];

// ---------------- helpers ----------------
__device__ __forceinline__ uint32_t f2tf32(float x) {
    uint32_t r; asm("cvt.rna.tf32.f32 %0, %1;" : "=r"(r) : "f"(x)); return r;
}
__device__ __forceinline__ void mma_tf32(float* c, const uint32_t* a, const uint32_t* b) {
    asm volatile("mma.sync.aligned.m16n8k8.row.col.f32.tf32.tf32.f32 "
        "{%0,%1,%2,%3}, {%4,%5,%6,%7}, {%8,%9}, {%0,%1,%2,%3};"
        : "+f"(c[0]), "+f"(c[1]), "+f"(c[2]), "+f"(c[3])
        : "r"(a[0]), "r"(a[1]), "r"(a[2]), "r"(a[3]), "r"(b[0]), "r"(b[1]));
}
__device__ __forceinline__ void cp16(void* s, const void* g, int sz) {
    uint32_t sa = (uint32_t)__cvta_generic_to_shared(s);
    asm volatile("cp.async.cg.shared.global [%0], [%1], 16, %2;" :: "r"(sa), "l"(g), "r"(sz));
}
__device__ __forceinline__ void cp4(void* s, const void* g, int sz) {
    uint32_t sa = (uint32_t)__cvta_generic_to_shared(s);
    asm volatile("cp.async.ca.shared.global [%0], [%1], 4, %2;" :: "r"(sa), "l"(g), "r"(sz));
}
__device__ __forceinline__ void cp_commit() { asm volatile("cp.async.commit_group;"); }
template<int Ng> __device__ __forceinline__ void cp_wait() {
    asm volatile("cp.async.wait_group %0;" :: "n"(Ng));
}

// ---------------- tf32 GEMM: 64x64xBK32, 128 thr, 3-stage cp.async ----------------
#define GT_BM 64
#define GT_BN 64
#define GT_BK 32
#define GT_SMEM (3 * 2304 * 2 * 4)

template<bool TRANSB, bool BIAS, bool TANH>
__global__ __launch_bounds__(128)
void gemm_tc(const float* __restrict__ A, const float* __restrict__ Bm,
             const float* __restrict__ bias, float* __restrict__ C,
             int M, int N, int K, int lda, int ldb, int ldc,
             long sA, long sB, long sC, float alpha)
{
    extern __shared__ float sm[];
    float* As = sm;                     // [3][64][36]  (row m, col k)
    float* Bs = sm + 3 * 2304;          // [3][32][72] (!T) or [3][64][36] (T)
    const int tid = threadIdx.x;
    const int wid = tid >> 5, lane = tid & 31;
    const int gid = lane >> 2, tig = lane & 3;
    const int m0 = blockIdx.y * GT_BM, n0 = blockIdx.x * GT_BN;
    A  += (long)blockIdx.z * sA;
    Bm += (long)blockIdx.z * sB;
    C  += (long)blockIdx.z * sC;
    const int wm0 = (wid & 1) * 32, wn0 = (wid >> 1) * 32;
    float acc[2][4][4] = {};

    const int ar = tid >> 1, akc = (tid & 1) * 16;   // A: row, k-chunk base (also T-B map)
    const int bkr = tid >> 2, bnc = (tid & 3) * 16;  // B(!T): k-row, n base
    const bool a_ok = (m0 + ar) < M;
    const bool b4 = (!TRANSB) && (((ldb & 3) != 0) || ((N & 3) != 0));
    const int nk = (K + GT_BK - 1) / GT_BK;

    auto issueA = [&](int kt, int st) {
        float* dst = As + st * 2304 + ar * 36 + akc;
        const float* src = A + (long)(m0 + ar) * lda + kt * GT_BK + akc;
        #pragma unroll
        for (int q = 0; q < 4; ++q) {
            int sz = (a_ok && (kt * GT_BK + akc + 4 * q) < K) ? 16 : 0;
            cp16(dst + 4 * q, src + 4 * q, sz);
        }
    };
    auto issueB = [&](int kt, int st) {
        if (!TRANSB) {
            float* dst = Bs + st * 2304 + bkr * 72 + bnc;
            const float* src = Bm + (long)(kt * GT_BK + bkr) * ldb + n0 + bnc;
            const bool kok = (kt * GT_BK + bkr) < K;
            if (!b4) {
                #pragma unroll
                for (int q = 0; q < 4; ++q) {
                    int sz = (kok && (n0 + bnc + 4 * q) < N) ? 16 : 0;
                    cp16(dst + 4 * q, src + 4 * q, sz);
                }
            } else {
                #pragma unroll
                for (int e = 0; e < 16; ++e) {
                    int sz = (kok && (n0 + bnc + e) < N) ? 4 : 0;
                    cp4(dst + e, src + e, sz);
                }
            }
        } else {
            float* dst = Bs + st * 2304 + ar * 36 + akc;
            const float* src = Bm + (long)(n0 + ar) * ldb + kt * GT_BK + akc;
            const bool nok = (n0 + ar) < N;
            #pragma unroll
            for (int q = 0; q < 4; ++q) {
                int sz = (nok && (kt * GT_BK + akc + 4 * q) < K) ? 16 : 0;
                cp16(dst + 4 * q, src + 4 * q, sz);
            }
        }
    };

    issueA(0, 0); issueB(0, 0); cp_commit();
    if (nk > 1) { issueA(1, 1); issueB(1, 1); }
    cp_commit();

    int st = 0;
    for (int kt = 0; kt < nk; ++kt) {
        cp_wait<1>();
        __syncthreads();
        const int ktn = kt + 2;
        if (ktn < nk) {
            const int stn = (st + 2 >= 3) ? st - 1 : st + 2;
            issueA(ktn, stn); issueB(ktn, stn);
        }
        cp_commit();
        const float* Ac = As + st * 2304;
        const float* Bc = Bs + st * 2304;
        #pragma unroll
        for (int kk = 0; kk < GT_BK; kk += 8) {
            uint32_t af[2][4], bf[4][2];
            #pragma unroll
            for (int mf = 0; mf < 2; ++mf) {
                const int r = wm0 + mf * 16;
                af[mf][0] = f2tf32(Ac[(r + gid) * 36 + kk + tig]);
                af[mf][1] = f2tf32(Ac[(r + 8 + gid) * 36 + kk + tig]);
                af[mf][2] = f2tf32(Ac[(r + gid) * 36 + kk + tig + 4]);
                af[mf][3] = f2tf32(Ac[(r + 8 + gid) * 36 + kk + tig + 4]);
            }
            #pragma unroll
            for (int nf = 0; nf < 4; ++nf) {
                const int c = wn0 + nf * 8 + gid;
                if (!TRANSB) {
                    bf[nf][0] = f2tf32(Bc[(kk + tig) * 72 + c]);
                    bf[nf][1] = f2tf32(Bc[(kk + tig + 4) * 72 + c]);
                } else {
                    bf[nf][0] = f2tf32(Bc[c * 36 + kk + tig]);
                    bf[nf][1] = f2tf32(Bc[c * 36 + kk + tig + 4]);
                }
            }
            #pragma unroll
            for (int mf = 0; mf < 2; ++mf)
                #pragma unroll
                for (int nf = 0; nf < 4; ++nf)
                    mma_tf32(acc[mf][nf], af[mf], bf[nf]);
        }
        st = (st + 1 >= 3) ? 0 : st + 1;
    }
    // ---- epilogue ----
    #pragma unroll
    for (int mf = 0; mf < 2; ++mf) {
        #pragma unroll
        for (int nf = 0; nf < 4; ++nf) {
            const int r = m0 + wm0 + mf * 16 + gid;
            const int c = n0 + wn0 + nf * 8 + tig * 2;
            #pragma unroll
            for (int half = 0; half < 2; ++half) {
                const int rr = r + half * 8;
                if (rr >= M) continue;
                #pragma unroll
                for (int j = 0; j < 2; ++j) {
                    const int cc = c + j;
                    if (cc >= N) continue;
                    float v = acc[mf][nf][half * 2 + j] * alpha;
                    if (BIAS) v += bias[cc];
                    if (TANH) v = tanhf(v);
                    C[(long)rr * ldc + cc] = v;
                }
            }
        }
    }
}

// ---------------- bilinear, factorized, 4-stage cp.async W pipeline ----------------
// C[m,n] = sum_{nb,i,j} Hs[m,nb*64+i]*Ts[m,nb*64+j]*W[(nb*4096+i*64+j), n] + bias[n]
#define BL_SMEM ((2*128*68 + 4*64*72) * 4)
__global__ __launch_bounds__(256)
void bilinear_tc(const float* __restrict__ Hs, const float* __restrict__ Ts,
                 const float* __restrict__ W, const float* __restrict__ bias,
                 float* __restrict__ C, int M)
{
    extern __shared__ float sm[];
    float* bh = sm;                      // [128][68]
    float* bt = sm + 128 * 68;           // [128][68]
    float* Ws = sm + 2 * 128 * 68;       // [4][64][72] fp32
    const int tid = threadIdx.x;
    const int wid = tid >> 5, lane = tid & 31;
    const int gid = lane >> 2, tig = lane & 3;
    const int m0 = blockIdx.y * 128, n0 = blockIdx.x * 64;
    const int wm0 = (wid & 3) * 32, wn0 = (wid >> 2) * 32;
    float acc[2][4][4] = {};
    const int lr = tid >> 1, lc = (tid & 1) * 32;
    const bool lok = (m0 + lr) < M;
    const int wr = tid >> 2, wc = (tid & 3) * 16;
    uint32_t btf[2][8][4];

#define LOADHT(nb_) { \
    const float* hp = Hs + (long)(m0 + lr) * 768 + (nb_) * 64 + lc; \
    const float* tp = Ts + (long)(m0 + lr) * 768 + (nb_) * 64 + lc; \
    _Pragma("unroll") for (int q_ = 0; q_ < 8; ++q_) { \
        float4 hv = lok ? *(const float4*)(hp + 4 * q_) : make_float4(0, 0, 0, 0); \
        float4 tv = lok ? *(const float4*)(tp + 4 * q_) : make_float4(0, 0, 0, 0); \
        *(float4*)&bh[lr * 68 + lc + 4 * q_] = hv; \
        *(float4*)&bt[lr * 68 + lc + 4 * q_] = tv; } }

#define ISSUEW(t_, st_) { \
    float* dst_ = Ws + (st_) * 4608 + wr * 72 + wc; \
    const float* src_ = W + ((long)(t_) * 64 + wr) * 768 + n0 + wc; \
    _Pragma("unroll") for (int q_ = 0; q_ < 4; ++q_) \
        cp16(dst_ + 4 * q_, src_ + 4 * q_, 16); }

#define CACHEBT() { \
    _Pragma("unroll") for (int mf_ = 0; mf_ < 2; ++mf_) { const int r0_ = wm0 + mf_ * 16; \
        _Pragma("unroll") for (int j0_ = 0; j0_ < 8; ++j0_) { \
            btf[mf_][j0_][0] = f2tf32(bt[(r0_ + gid) * 68 + j0_ * 8 + tig]); \
            btf[mf_][j0_][1] = f2tf32(bt[(r0_ + 8 + gid) * 68 + j0_ * 8 + tig]); \
            btf[mf_][j0_][2] = f2tf32(bt[(r0_ + gid) * 68 + j0_ * 8 + tig + 4]); \
            btf[mf_][j0_][3] = f2tf32(bt[(r0_ + 8 + gid) * 68 + j0_ * 8 + tig + 4]); } } }

    LOADHT(0);
    ISSUEW(0, 0); cp_commit();
    ISSUEW(1, 1); cp_commit();
    ISSUEW(2, 2); cp_commit();
    __syncthreads();
    CACHEBT();

    for (int t = 0; t < NBn * 64; ++t) {
        const int st = t & 3;
        cp_wait<2>();
        __syncthreads();
        if (t + 3 < NBn * 64) { ISSUEW(t + 3, (t + 3) & 3); }
        cp_commit();
        const float* Wc = Ws + st * 4608;
        const int i = t & 63;
        float D[2][4][4] = {};
        #pragma unroll
        for (int j0 = 0; j0 < 8; ++j0) {
            uint32_t bf[4][2];
            #pragma unroll
            for (int nf = 0; nf < 4; ++nf) {
                bf[nf][0] = f2tf32(Wc[(j0 * 8 + tig) * 72 + wn0 + nf * 8 + gid]);
                bf[nf][1] = f2tf32(Wc[(j0 * 8 + tig + 4) * 72 + wn0 + nf * 8 + gid]);
            }
            #pragma unroll
            for (int mf = 0; mf < 2; ++mf)
                #pragma unroll
                for (int nf = 0; nf < 4; ++nf)
                    mma_tf32(D[mf][nf], btf[mf][j0], bf[nf]);
        }
        #pragma unroll
        for (int mf = 0; mf < 2; ++mf) {
            const float b0 = bh[(wm0 + mf * 16 + gid) * 68 + i];
            const float b1 = bh[(wm0 + mf * 16 + 8 + gid) * 68 + i];
            #pragma unroll
            for (int nf = 0; nf < 4; ++nf) {
                acc[mf][nf][0] = fmaf(b0, D[mf][nf][0], acc[mf][nf][0]);
                acc[mf][nf][1] = fmaf(b0, D[mf][nf][1], acc[mf][nf][1]);
                acc[mf][nf][2] = fmaf(b1, D[mf][nf][2], acc[mf][nf][2]);
                acc[mf][nf][3] = fmaf(b1, D[mf][nf][3], acc[mf][nf][3]);
            }
        }
        if ((t & 63) == 63 && t + 1 < NBn * 64) {
            __syncthreads();
            LOADHT((t + 1) >> 6);
            __syncthreads();
            CACHEBT();
        }
    }
#undef LOADHT
#undef ISSUEW
#undef CACHEBT
    #pragma unroll
    for (int mf = 0; mf < 2; ++mf) {
        #pragma unroll
        for (int nf = 0; nf < 4; ++nf) {
            const int r = m0 + wm0 + mf * 16 + gid;
            const int c = n0 + wn0 + nf * 8 + tig * 2;
            if (r < M) {
                C[(long)r * 768 + c]     = acc[mf][nf][0] + bias[c];
                C[(long)r * 768 + c + 1] = acc[mf][nf][1] + bias[c + 1];
            }
            if (r + 8 < M) {
                C[(long)(r + 8) * 768 + c]     = acc[mf][nf][2] + bias[c];
                C[(long)(r + 8) * 768 + c + 1] = acc[mf][nf][3] + bias[c + 1];
            }
        }
    }
}

// ---------------- small fused kernels ----------------
__global__ void ent_emb_k(const float* __restrict__ seq, const int* __restrict__ midx,
                          const float* __restrict__ mmask, float* __restrict__ ent_emb)
{
    const int blk = blockIdx.x;
    const int b = blk / (MMn * NEn);
    const int idx = midx[blk];
    const float mask = mmask[blk];
    const float* src = seq + ((long)b * Cn + idx) * Hn;
    float* dst = ent_emb + (long)blk * Hn;
    for (int h = threadIdx.x; h < Hn; h += 256) dst[h] = mask * src[h];
}

__global__ void ent_att_k(const float* __restrict__ att, const int* __restrict__ midx,
                          const float* __restrict__ mmask, float* __restrict__ ent_att)
{
    const int blk = blockIdx.x;
    const int nh = blk % NHn;
    const int e  = (blk / NHn) % NEn;
    const int b  = blk / (NHn * NEn);
    const int c  = threadIdx.x;
    const int* mi = midx + (b * NEn + e) * MMn;
    const float* mk = mmask + (b * NEn + e) * MMn;
    float cnt = 0.f, s = 0.f;
    for (int m = 0; m < MMn; ++m) {
        const float w = mk[m];
        cnt += w;
        s += w * att[(((long)b * NHn + nh) * Cn + mi[m]) * Cn + c];
    }
    ent_att[(long)blk * Cn + c] = s / cnt;
}

__global__ void ht_att_k(const float* __restrict__ ent_att, const int* __restrict__ hts,
                         float* __restrict__ ht_att)
{
    const int bp = blockIdx.x;
    const int b = bp / Pn;
    const int hi = hts[bp * 2], ti = hts[bp * 2 + 1];
    const int c = threadIdx.x;
    const float* ha = ent_att + (long)(b * NEn + hi) * NHn * Cn;
    const float* ta = ent_att + (long)(b * NEn + ti) * NHn * Cn;
    float v = 0.f;
    #pragma unroll
    for (int nh = 0; nh < NHn; ++nh) v += ha[nh * Cn + c] * ta[nh * Cn + c];
    v *= (1.f / 12.f);
    __shared__ float red[512];
    red[c] = v; __syncthreads();
    for (int s = 256; s > 0; s >>= 1) { if (c < s) red[c] += red[c + s]; __syncthreads(); }
    ht_att[(long)bp * Cn + c] = v / (red[0] + 1e-5f);
}

__global__ void pool_attn_k(const float* __restrict__ htq, const float* __restrict__ ent_q,
                            const float* __restrict__ ent_emb, const float* __restrict__ mmask,
                            const int* __restrict__ hts, float* __restrict__ hs_att,
                            float* __restrict__ ts_att)
{
    const int bp = blockIdx.x;
    const int side = blockIdx.y;
    const int b = bp / Pn;
    const int e = hts[bp * 2 + side];
    __shared__ float qs[QSn];
    __shared__ float gs[MMn];
    const int tid = threadIdx.x;
    if (tid < QSn) qs[tid] = htq[(long)bp * QSn + tid];
    __syncthreads();
    if (tid < MMn) {
        const float* eq = ent_q + ((long)(b * NEn + e) * MMn + tid) * QSn;
        float d = 0.f;
        for (int i = 0; i < QSn; ++i) d += qs[i] * eq[i];
        const float mk = mmask[(b * NEn + e) * MMn + tid];
        gs[tid] = (mk > 0.f) ? d * SCALE_EMB : kNEG;
    }
    __syncthreads();
    float mx = -1e30f;
    for (int m = 0; m < MMn; ++m) mx = fmaxf(mx, gs[m]);
    float w[MMn]; float ssum = 0.f;
    for (int m = 0; m < MMn; ++m) { w[m] = expf(gs[m] - mx); ssum += w[m]; }
    const float inv = 1.f / ssum;
    const float* emb = ent_emb + (long)(b * NEn + e) * MMn * Hn;
    float* out = (side ? ts_att : hs_att) + (long)bp * Hn;
    for (int h = tid; h < Hn; h += 256) {
        float acc2 = 0.f;
        for (int m = 0; m < MMn; ++m) acc2 += w[m] * emb[m * Hn + h];
        out[h] = acc2 * inv;
    }
}

__global__ void cat2_k(const float* __restrict__ hs_att, const float* __restrict__ ts_att,
                       const float* __restrict__ rs, float* __restrict__ cat_h,
                       float* __restrict__ cat_t)
{
    const long r = blockIdx.x;
    for (int h = threadIdx.x; h < Hn; h += 256) {
        const float rv = rs[r * Hn + h];
        cat_h[r * 1536 + h]       = hs_att[r * Hn + h];
        cat_h[r * 1536 + 768 + h] = rv;
        cat_t[r * 1536 + h]       = ts_att[r * Hn + h];
        cat_t[r * 1536 + 768 + h] = rv;
    }
}

__global__ void catpp_k(const float* __restrict__ pairg, const float* __restrict__ pos_emb,
                        const int* __restrict__ hts, float* __restrict__ catpp)
{
    const long r = blockIdx.x;
    const int hi = hts[r * 2], ti = hts[r * 2 + 1];
    if (threadIdx.x < POSn) {
        catpp[r * 1024 + threadIdx.x]       = pos_emb[hi * POSn + threadIdx.x];
        catpp[r * 1024 + 896 + threadIdx.x] = pos_emb[ti * POSn + threadIdx.x];
    }
    for (int h = threadIdx.x; h < Hn; h += 256)
        catpp[r * 1024 + 128 + h] = pairg[r * Hn + h];
}

__global__ void pair_softmax_k(float* __restrict__ sc, const float* __restrict__ vis)
{
    const long bp = blockIdx.x;
    float* row = sc + bp * Pn;
    const float* vr = vis + bp * Pn;
    const int tid = threadIdx.x;
    __shared__ float red[128];
    float mx = -1e30f;
    for (int q = tid; q < Pn; q += 128) {
        const float v = (vr[q] > 0.f) ? row[q] : kNEG;
        mx = fmaxf(mx, v);
    }
    red[tid] = mx; __syncthreads();
    for (int s = 64; s > 0; s >>= 1) { if (tid < s) red[tid] = fmaxf(red[tid], red[tid + s]); __syncthreads(); }
    mx = red[0]; __syncthreads();
    float sum = 0.f;
    for (int q = tid; q < Pn; q += 128) {
        const float v = (vr[q] > 0.f) ? row[q] : kNEG;
        sum += expf(v - mx);
    }
    red[tid] = sum; __syncthreads();
    for (int s = 64; s > 0; s >>= 1) { if (tid < s) red[tid] += red[tid + s]; __syncthreads(); }
    const float inv = 1.f / red[0];
    for (int q = tid; q < Pn; q += 128) {
        const float v = (vr[q] > 0.f) ? row[q] : kNEG;
        row[q] = expf(v - mx) * inv;
    }
}

__global__ void catfeat_k(const float* __restrict__ hs, const float* __restrict__ ts,
                          const float* __restrict__ pair1, const float* __restrict__ atto,
                          float* __restrict__ catf)
{
    const long r = blockIdx.x;
    for (int h = threadIdx.x; h < Hn; h += 256) {
        catf[r * 2304 + h]        = hs[r * Hn + h];
        catf[r * 2304 + 768 + h]  = ts[r * Hn + h];
        catf[r * 2304 + 1536 + h] = pair1[r * Hn + h] + atto[r * Hn + h];
    }
}

// ---------------- launcher ----------------
extern "C" void kernel_launch(void* const* d_in, const int* in_sizes, int n_in,
                              void* d_out, int out_size)
{
    (void)in_sizes; (void)n_in; (void)out_size;
    const float* seq   = (const float*)d_in[0];
    const float* att   = (const float*)d_in[1];
    const int*   midx  = (const int*)  d_in[2];
    const float* mmask = (const float*)d_in[3];
    const int*   hts   = (const int*)  d_in[4];
    const float* vis   = (const float*)d_in[5];
    const float* Wcq = (const float*)d_in[6],  *bcq = (const float*)d_in[7];
    const float* Weq = (const float*)d_in[8],  *beq = (const float*)d_in[9];
    const float* Whe = (const float*)d_in[10], *bhe = (const float*)d_in[11];
    const float* Wte = (const float*)d_in[12], *bte = (const float*)d_in[13];
    const float* Wbl = (const float*)d_in[14], *bbl = (const float*)d_in[15];
    const float* Wpp = (const float*)d_in[16], *bpp = (const float*)d_in[17];
    const float* Wgq = (const float*)d_in[18];
    const float* Wgk = (const float*)d_in[19];
    const float* Wgv = (const float*)d_in[20];
    const float* Wp1 = (const float*)d_in[21], *bp1 = (const float*)d_in[22];
    const float* Wp2 = (const float*)d_in[23], *bp2 = (const float*)d_in[24];
    const float* pos = (const float*)d_in[25];
    float* out = (float*)d_out;

    float* base = nullptr;
    cudaGetSymbolAddress((void**)&base, g_scratch);
    float* ent_emb = base + OFF_ENT_EMB;
    float* ent_att = base + OFF_ENT_ATT;
    float* ent_q   = base + OFF_ENT_Q;
    float* ht_att  = base + OFF_HT_ATT;
    float* rs      = base + OFF_RS;
    float* htqb    = base + OFF_HTQ;
    float* hs_att  = base + OFF_HS_ATT;
    float* ts_att  = base + OFF_TS_ATT;
    float* cat_h   = base + OFF_CAT_H;
    float* cat_t   = base + OFF_CAT_T;
    float* hs_t    = base + OFF_HS;
    float* ts_t    = base + OFF_TS;
    float* pairg   = base + OFF_PAIRG;
    float* catpp   = base + OFF_CATPP;
    float* pair1   = base + OFF_PAIR1;
    float* qb      = base + OFF_QB;
    float* kb      = base + OFF_KB;
    float* vb      = base + OFF_VB;
    float* scb     = base + OFF_SC;
    float* atto    = base + OFF_ATTO;
    float* catf    = base + OFF_CATF;
    float* h1      = base + OFF_H1;

    cudaFuncSetAttribute(gemm_tc<false,false,false>, cudaFuncAttributeMaxDynamicSharedMemorySize, GT_SMEM);
    cudaFuncSetAttribute(gemm_tc<false,true,false>,  cudaFuncAttributeMaxDynamicSharedMemorySize, GT_SMEM);
    cudaFuncSetAttribute(gemm_tc<false,true,true>,   cudaFuncAttributeMaxDynamicSharedMemorySize, GT_SMEM);
    cudaFuncSetAttribute(gemm_tc<true,false,false>,  cudaFuncAttributeMaxDynamicSharedMemorySize, GT_SMEM);
    cudaFuncSetAttribute(bilinear_tc, cudaFuncAttributeMaxDynamicSharedMemorySize, BL_SMEM);

    // 1) entity gathers
    ent_emb_k<<<Bn * NEn * MMn, 256>>>(seq, midx, mmask, ent_emb);
    ent_att_k<<<Bn * NEn * NHn, 512>>>(att, midx, mmask, ent_att);
    // 2) pair context attention
    ht_att_k<<<BPn, 512>>>(ent_att, hts, ht_att);
    // 3) rs = ht_att @ seq (batched)
    gemm_tc<false,false,false><<<dim3(12, 6, 4), 128, GT_SMEM>>>(ht_att, seq, nullptr, rs,
        Pn, Hn, Cn, Cn, Hn, Hn, 380L*512, 512L*768, 380L*768, 1.f);
    // 4) htq, ent_q
    gemm_tc<false,true,false><<<dim3(2, 24, 1), 128, GT_SMEM>>>(rs, Wcq, bcq, htqb,
        BPn, QSn, Hn, Hn, QSn, QSn, 0, 0, 0, 1.f);
    gemm_tc<false,true,false><<<dim3(2, 29, 1), 128, GT_SMEM>>>(ent_emb, Weq, beq, ent_q,
        1840, QSn, Hn, Hn, QSn, QSn, 0, 0, 0, 1.f);
    // 5) mention-pool softmax
    pool_attn_k<<<dim3(BPn, 2), 256>>>(htqb, ent_q, ent_emb, mmask, hts, hs_att, ts_att);
    // 6) hs/ts projections
    cat2_k<<<BPn, 256>>>(hs_att, ts_att, rs, cat_h, cat_t);
    gemm_tc<false,true,true><<<dim3(12, 24, 1), 128, GT_SMEM>>>(cat_h, Whe, bhe, hs_t,
        BPn, EMBn, 1536, 1536, EMBn, EMBn, 0, 0, 0, 1.f);
    gemm_tc<false,true,true><<<dim3(12, 24, 1), 128, GT_SMEM>>>(cat_t, Wte, bte, ts_t,
        BPn, EMBn, 1536, 1536, EMBn, EMBn, 0, 0, 0, 1.f);
    // 7) grouped bilinear
    bilinear_tc<<<dim3(12, 12), 256, BL_SMEM>>>(hs_t, ts_t, Wbl, bbl, pairg, BPn);
    // 8) pos concat + Wpp
    catpp_k<<<BPn, 256>>>(pairg, pos, hts, catpp);
    gemm_tc<false,true,true><<<dim3(12, 24, 1), 128, GT_SMEM>>>(catpp, Wpp, bpp, pair1,
        BPn, EMBn, 1024, 1024, EMBn, EMBn, 0, 0, 0, 1.f);
    // 9) pair-graph attention
    gemm_tc<false,false,false><<<dim3(12, 24, 1), 128, GT_SMEM>>>(pair1, Wgq, nullptr, qb,
        BPn, EMBn, EMBn, EMBn, EMBn, EMBn, 0, 0, 0, 1.f);
    gemm_tc<false,false,false><<<dim3(12, 24, 1), 128, GT_SMEM>>>(pair1, Wgk, nullptr, kb,
        BPn, EMBn, EMBn, EMBn, EMBn, EMBn, 0, 0, 0, 1.f);
    gemm_tc<false,false,false><<<dim3(12, 24, 1), 128, GT_SMEM>>>(pair1, Wgv, nullptr, vb,
        BPn, EMBn, EMBn, EMBn, EMBn, EMBn, 0, 0, 0, 1.f);
    gemm_tc<true,false,false><<<dim3(6, 6, 4), 128, GT_SMEM>>>(qb, kb, nullptr, scb,
        Pn, Pn, EMBn, EMBn, EMBn, Pn, 380L*768, 380L*768, 380L*380, SCALE_EMB);
    pair_softmax_k<<<BPn, 128>>>(scb, vis);
    gemm_tc<false,false,false><<<dim3(12, 6, 4), 128, GT_SMEM>>>(scb, vb, nullptr, atto,
        Pn, EMBn, Pn, Pn, EMBn, EMBn, 380L*380, 380L*768, 380L*768, 1.f);
    // 10) classifier head
    catfeat_k<<<BPn, 256>>>(hs_t, ts_t, pair1, atto, catf);
    gemm_tc<false,true,true><<<dim3(12, 24, 1), 128, GT_SMEM>>>(catf, Wp1, bp1, h1,
        BPn, EMBn, 2304, 2304, EMBn, EMBn, 0, 0, 0, 1.f);
    gemm_tc<false,true,false><<<dim3(2, 24, 1), 128, GT_SMEM>>>(h1, Wp2, bp2, out,
        BPn, NCLSn, EMBn, EMBn, NCLSn, NCLSn, 0, 0, 0, 1.f);
}